// round 1
// baseline (speedup 1.0000x reference)
#include <cuda_runtime.h>
#include <cstdint>

#define DIMC 1024
#define HIDC 64
#define NBC  64
#define KC   128
#define NCHUNK (DIMC / KC)        // 8
#define TPB  64                   // tokens per block
#define NTHREADS 256

#define XS_WORDS (KC * 128)       // 16384 floats: x tile, duplicated, swizzled  (64 KB)
#define WS_WORDS (KC * 64)        //  8192 floats: W tile, swizzled              (32 KB)
#define SMEM_BYTES ((XS_WORDS + WS_WORDS) * 4)   // 98304 B

#define FMA2(acc, a, b) asm("fma.rn.f32x2 %0, %1, %2, %0;" : "+l"(acc) : "l"(a), "l"(b))

__global__ void __launch_bounds__(NTHREADS, 2)
rbf_fused_kernel(const float* __restrict__ x,
                 const float* __restrict__ in_w,
                 const float* __restrict__ in_b,
                 const float* __restrict__ centers,
                 const float* __restrict__ log_widths,
                 const float* __restrict__ out_weight,
                 const float* __restrict__ out_bias,
                 float* __restrict__ out)
{
    extern __shared__ float sm[];
    float* xs = sm;                 // [KC][128]  (row = k, col = swizzled dup'd token)
    float* ws = sm + XS_WORDS;      // [KC][64]   (row = k, col = swizzled h)
    const unsigned xs_b = (unsigned)__cvta_generic_to_shared(xs);
    const unsigned ws_b = (unsigned)__cvta_generic_to_shared(ws);

    const int tid = threadIdx.x;
    const int tx  = tid & 15;       // h group:  h = 4*tx + j
    const int ty  = tid >> 4;       // token grp: t = 4*ty + i
    const int tok0 = blockIdx.x * TPB;

    // accumulators: 2 f32x2 h-pairs x 4 tokens (pair = (4tx+2hp, 4tx+2hp+1))
    unsigned long long acc[2][4];
#pragma unroll
    for (int hp = 0; hp < 2; ++hp)
#pragma unroll
        for (int t = 0; t < 4; ++t) acc[hp][t] = 0ull;

    const float4* xg = (const float4*)x;
    const float4* wg = (const float4*)in_w;

    for (int ch = 0; ch < NCHUNK; ++ch) {
        if (ch) __syncthreads();

        // ---- load x chunk: 64 tok x 128 ch, transposed + duplicated + swizzled ----
        // element x[t][c]  ->  xs[row=c][ 4*((t>>1) ^ ((c>>2)&7)) + 2*(t&1) + {0,1} ]
#pragma unroll
        for (int r = 0; r < 8; ++r) {
            int i  = r * NTHREADS + tid;           // 0..2047
            int j3 = i & 7;
            int g  = i >> 3;
            int t  = g & 63;
            int c4 = ((g >> 6) << 3) + j3;         // 0..31 (chunk-local c/4)
            float4 v = xg[(tok0 + t) * (DIMC / 4) + ch * (KC / 4) + c4];
            int off = 4 * ((t >> 1) ^ (c4 & 7)) + 2 * (t & 1);
            float vv[4] = {v.x, v.y, v.z, v.w};
#pragma unroll
            for (int jj = 0; jj < 4; ++jj) {
                float2* p = (float2*)(xs + (c4 * 4 + jj) * 128 + off);
                *p = make_float2(vv[jj], vv[jj]);
            }
        }
        // ---- load W chunk: 64 h x 128 ch, transposed + swizzled ----
        // element W[h][c] -> ws[row=c][ 4*((h>>2) ^ ((c>>2)&15)) + (h&3) ]
#pragma unroll
        for (int r = 0; r < 8; ++r) {
            int i  = r * NTHREADS + tid;
            int j3 = i & 7;
            int g  = i >> 3;
            int h  = g & 63;
            int c4 = ((g >> 6) << 3) + j3;
            float4 v = wg[h * (DIMC / 4) + ch * (KC / 4) + c4];
            int col = 4 * ((h >> 2) ^ (c4 & 15)) + (h & 3);
            float vv[4] = {v.x, v.y, v.z, v.w};
#pragma unroll
            for (int jj = 0; jj < 4; ++jj)
                ws[(c4 * 4 + jj) * 64 + col] = vv[jj];
        }
        __syncthreads();

        // ---- FFMA2 mainloop over 128 k values ----
#pragma unroll 2
        for (int k4 = 0; k4 < KC / 4; ++k4) {
            const int keyw = k4 & 15;
            const int key7 = k4 & 7;
            const unsigned aw  = ws_b + (unsigned)((k4 * 4) * 64  + 4 * (tx ^ keyw)) * 4u;
            const unsigned ax0 = xs_b + (unsigned)((k4 * 4) * 128 + 4 * ((2 * ty)     ^ key7)) * 4u;
            const unsigned ax1 = xs_b + (unsigned)((k4 * 4) * 128 + 4 * ((2 * ty + 1) ^ key7)) * 4u;
#pragma unroll
            for (int u = 0; u < 4; ++u) {
                unsigned long long w01, w23, x0, x1, x2, x3;
                asm volatile("ld.shared.v2.b64 {%0,%1}, [%2];"
                             : "=l"(w01), "=l"(w23) : "r"(aw + u * 256u));
                asm volatile("ld.shared.v2.b64 {%0,%1}, [%2];"
                             : "=l"(x0), "=l"(x1) : "r"(ax0 + u * 512u));
                asm volatile("ld.shared.v2.b64 {%0,%1}, [%2];"
                             : "=l"(x2), "=l"(x3) : "r"(ax1 + u * 512u));
                FMA2(acc[0][0], w01, x0); FMA2(acc[0][1], w01, x1);
                FMA2(acc[0][2], w01, x2); FMA2(acc[0][3], w01, x3);
                FMA2(acc[1][0], w23, x0); FMA2(acc[1][1], w23, x1);
                FMA2(acc[1][2], w23, x2); FMA2(acc[1][3], w23, x3);
            }
        }
    }

    // ---- unpack z and add input bias ----
    float z[4][4];                                // [token][h offset j]
#pragma unroll
    for (int hp = 0; hp < 2; ++hp)
#pragma unroll
        for (int t = 0; t < 4; ++t) {
            float lo, hi;
            asm("mov.b64 {%0,%1}, %2;" : "=f"(lo), "=f"(hi) : "l"(acc[hp][t]));
            z[t][2 * hp]     = lo;
            z[t][2 * hp + 1] = hi;
        }
    {
        float4 bb = ((const float4*)in_b)[tx];
        float bj[4] = {bb.x, bb.y, bb.z, bb.w};
#pragma unroll
        for (int t = 0; t < 4; ++t)
#pragma unroll
            for (int j = 0; j < 4; ++j) z[t][j] += bj[j];
    }

    // ---- stage RBF params into smem: [k][h] layout, conflict-free float4 reads ----
    __syncthreads();
    float* ps_c = sm;            // 4096 floats
    float* ps_s = sm + 4096;     // 4096 floats: -log2(e)/width^2
    float* ps_w = sm + 8192;     // 4096 floats
    for (int i = tid; i < HIDC * NBC; i += NTHREADS) {
        int k = i >> 6;
        int h = i & 63;
        float lw = log_widths[h * NBC + k];
        float sp = (lw > 15.f) ? lw : log1pf(expf(lw));
        float w  = sp + 0.001f;
        ps_c[i] = centers[h * NBC + k];
        ps_s[i] = -1.4426950408889634f / (w * w);
        ps_w[i] = out_weight[h * NBC + k];
    }
    __syncthreads();

    // ---- RBF epilogue: 64 basis x (4 h x 4 tokens) per thread ----
    float sc[4] = {0.f, 0.f, 0.f, 0.f};
#pragma unroll 2
    for (int k = 0; k < NBC; ++k) {
        float4 cc = ((const float4*)ps_c)[k * 16 + tx];
        float4 ss = ((const float4*)ps_s)[k * 16 + tx];
        float4 ww = ((const float4*)ps_w)[k * 16 + tx];
        float cj[4] = {cc.x, cc.y, cc.z, cc.w};
        float sj[4] = {ss.x, ss.y, ss.z, ss.w};
        float wj[4] = {ww.x, ww.y, ww.z, ww.w};
#pragma unroll
        for (int j = 0; j < 4; ++j)
#pragma unroll
            for (int t = 0; t < 4; ++t) {
                float u  = z[t][j] - cj[j];
                float p  = (u * u) * sj[j];        // = -(z-c)^2 * log2e / w^2
                float e;
                asm("ex2.approx.f32 %0, %1;" : "=f"(e) : "f"(p));
                sc[t] = fmaf(e, wj[j], sc[t]);
            }
    }

    // ---- reduce over the 16 tx lanes (h dimension), write output ----
    const float ob = __ldg(out_bias);
#pragma unroll
    for (int t = 0; t < 4; ++t) {
        float v = sc[t];
        v += __shfl_xor_sync(0xffffffffu, v, 1);
        v += __shfl_xor_sync(0xffffffffu, v, 2);
        v += __shfl_xor_sync(0xffffffffu, v, 4);
        v += __shfl_xor_sync(0xffffffffu, v, 8);
        if (tx == 0) out[tok0 + ty * 4 + t] = v + ob;
    }
}

extern "C" void kernel_launch(void* const* d_in, const int* in_sizes, int n_in,
                              void* d_out, int out_size)
{
    const float* x          = (const float*)d_in[0];
    const float* in_w       = (const float*)d_in[1];
    const float* in_b       = (const float*)d_in[2];
    const float* centers    = (const float*)d_in[3];
    const float* log_widths = (const float*)d_in[4];
    const float* out_weight = (const float*)d_in[5];
    const float* out_bias   = (const float*)d_in[6];
    float* out = (float*)d_out;

    int ntok = in_sizes[0] / DIMC;      // 65536
    int grid = ntok / TPB;              // 1024

    cudaFuncSetAttribute(rbf_fused_kernel,
                         cudaFuncAttributeMaxDynamicSharedMemorySize, SMEM_BYTES);
    rbf_fused_kernel<<<grid, NTHREADS, SMEM_BYTES>>>(
        x, in_w, in_b, centers, log_widths, out_weight, out_bias, out);
}

// round 3
// speedup vs baseline: 1.7922x; 1.7922x over previous
#include <cuda_runtime.h>
#include <cstdint>

#define NTHREADS 128
#define MTILE    128
#define KCHUNK   64
#define NCHUNKS  16
#define NH       64
#define NB       64
#define DIMC     1024
#define ZSTRIDE  66            // padded z row stride in floats

// smem byte layout
#define OFF_AHI  0
#define OFF_ALO  16384
#define OFF_BHI  32768
#define OFF_BLO  40960
#define OFF_Q    49152         // 4096 float4 = 65536 B
#define SMEM_TOTAL (OFF_Q + 65536)   // 114688 B

__device__ float4 g_q[NH * NB];

static __device__ __forceinline__ uint32_t smem_u32(const void* p) {
    uint32_t a;
    asm("{ .reg .u64 t; cvta.to.shared.u64 t, %1; cvt.u32.u64 %0, t; }" : "=r"(a) : "l"(p));
    return a;
}

// split float4 (4 consecutive k) into bf16 hi/lo packs, store 8B each
static __device__ __forceinline__ void split_store(float4 v, uint32_t ahi, uint32_t alo) {
    uint32_t u0 = __float_as_uint(v.x), u1 = __float_as_uint(v.y);
    uint32_t u2 = __float_as_uint(v.z), u3 = __float_as_uint(v.w);
    uint32_t hi01 = __byte_perm(u0, u1, 0x7632);
    uint32_t hi23 = __byte_perm(u2, u3, 0x7632);
    float l0 = v.x - __uint_as_float(u0 & 0xffff0000u);
    float l1 = v.y - __uint_as_float(u1 & 0xffff0000u);
    float l2 = v.z - __uint_as_float(u2 & 0xffff0000u);
    float l3 = v.w - __uint_as_float(u3 & 0xffff0000u);
    uint32_t lo01, lo23;
    asm("cvt.rn.bf16x2.f32 %0, %1, %2;" : "=r"(lo01) : "f"(l1), "f"(l0));
    asm("cvt.rn.bf16x2.f32 %0, %1, %2;" : "=r"(lo23) : "f"(l3), "f"(l2));
    asm volatile("st.shared.v2.b32 [%0], {%1,%2};" :: "r"(ahi), "r"(hi01), "r"(hi23) : "memory");
    asm volatile("st.shared.v2.b32 [%0], {%1,%2};" :: "r"(alo), "r"(lo01), "r"(lo23) : "memory");
}

#define LDSM4(r0, r1, r2, r3, a) \
    asm volatile("ldmatrix.sync.aligned.m8n8.x4.shared.b16 {%0,%1,%2,%3}, [%4];" \
                 : "=r"(r0), "=r"(r1), "=r"(r2), "=r"(r3) : "r"(a))

#define MMA(c, a0, a1, a2, a3, b0, b1) \
    asm volatile("mma.sync.aligned.m16n8k16.row.col.f32.bf16.bf16.f32 " \
                 "{%0,%1,%2,%3}, {%4,%5,%6,%7}, {%8,%9}, {%0,%1,%2,%3};" \
                 : "+f"((c)[0]), "+f"((c)[1]), "+f"((c)[2]), "+f"((c)[3]) \
                 : "r"(a0), "r"(a1), "r"(a2), "r"(a3), "r"(b0), "r"(b1))

// ---- prep kernel: RBF coeff table {s, -2sc', sc'^2, ow} ----
__global__ void rbf_prep_kernel(const float* __restrict__ in_b,
                                const float* __restrict__ centers,
                                const float* __restrict__ log_widths,
                                const float* __restrict__ out_weight)
{
    int i = blockIdx.x * blockDim.x + threadIdx.x;
    if (i >= NH * NB) return;
    int h = i >> 6;
    float lw = log_widths[i];
    float sp = (lw > 15.f) ? lw : log1pf(expf(lw));
    float w = sp + 0.001f;
    float s = -1.4426950408889634f / (w * w);    // -log2(e)/w^2
    float c = centers[i] - in_b[h];              // fold bias into center
    float4 q;
    q.x = s; q.y = -2.f * s * c; q.z = s * c * c; q.w = out_weight[i];
    g_q[i] = q;
}

__global__ void __launch_bounds__(NTHREADS, 2)
rbf_main_kernel(const float* __restrict__ x,
                const float* __restrict__ in_w,
                const float* __restrict__ out_bias,
                float* __restrict__ out)
{
    extern __shared__ char smem[];
    const uint32_t sb = smem_u32(smem);
    const int tid = threadIdx.x;
    const int w   = tid >> 5;
    const int l   = tid & 31;
    const int tok0 = blockIdx.x * MTILE;

    // ---- stage coeff table (global -> smem), consumed after GEMM ----
    {
        const float4* gq = g_q;
        float4* qs = (float4*)(smem + OFF_Q);
#pragma unroll
        for (int i = 0; i < 32; ++i) qs[i * NTHREADS + tid] = gq[i * NTHREADS + tid];
    }

    // ---- per-thread staging constants ----
    const int r0  = tid >> 4;          // base row phase (0..7)
    const int c4  = tid & 15;          // float4 k-column
    const uint32_t kk = (uint32_t)(r0 & 7) << 4;   // swizzle key for stores
    const uint32_t stc = (uint32_t)c4 * 8u;

    // ---- per-thread ldmatrix constants ----
    const uint32_t key = (uint32_t)(l & 7);
    const uint32_t rowA = (uint32_t)(w * 32 + (l & 15));     // + m*16
    const uint32_t chA  = (uint32_t)((l >> 4) & 1);
    const uint32_t rowB = (uint32_t)(((l >> 4) << 3) + (l & 7)); // + nt*8
    const uint32_t chB  = (uint32_t)((l >> 3) & 1);

    float acc[2][8][4];
#pragma unroll
    for (int m = 0; m < 2; ++m)
#pragma unroll
        for (int nt = 0; nt < 8; ++nt)
#pragma unroll
            for (int j = 0; j < 4; ++j) acc[m][nt][j] = 0.f;

    const float4* xg = (const float4*)x;
    const float4* wg = (const float4*)in_w;

#pragma unroll 1
    for (int ch = 0; ch < NCHUNKS; ++ch) {
        // ---- A tile: 128 tok x 64 k ----
#pragma unroll
        for (int it = 0; it < 16; ++it) {
            int row = r0 + it * 8;
            float4 v = xg[(long)(tok0 + row) * 256 + ch * 16 + c4];
            uint32_t sw = ((uint32_t)row * 128u + stc) ^ kk;
            split_store(v, sb + OFF_AHI + sw, sb + OFF_ALO + sw);
        }
        // ---- B tile: 64 h x 64 k ----
#pragma unroll
        for (int it = 0; it < 8; ++it) {
            int row = r0 + it * 8;
            float4 v = wg[(long)row * 256 + ch * 16 + c4];
            uint32_t sw = ((uint32_t)row * 128u + stc) ^ kk;
            split_store(v, sb + OFF_BHI + sw, sb + OFF_BLO + sw);
        }
        __syncthreads();

#pragma unroll
        for (int s = 0; s < 4; ++s) {
            const uint32_t colA = ((uint32_t)(s * 2) + chA) ^ key;
            const uint32_t colB = ((uint32_t)(s * 2) + chB) ^ key;
            uint32_t ah[2][4], al[2][4];
#pragma unroll
            for (int m = 0; m < 2; ++m) {
                uint32_t ra = (rowA + m * 16) * 128u + (colA << 4);
                LDSM4(ah[m][0], ah[m][1], ah[m][2], ah[m][3], sb + OFF_AHI + ra);
                LDSM4(al[m][0], al[m][1], al[m][2], al[m][3], sb + OFF_ALO + ra);
            }
#pragma unroll
            for (int np = 0; np < 4; ++np) {
                uint32_t rb = (rowB + np * 16) * 128u + (colB << 4);
                uint32_t bh[4], bl[4];
                LDSM4(bh[0], bh[1], bh[2], bh[3], sb + OFF_BHI + rb);
                LDSM4(bl[0], bl[1], bl[2], bl[3], sb + OFF_BLO + rb);
#pragma unroll
                for (int m = 0; m < 2; ++m) {
                    MMA(acc[m][2 * np],     ah[m][0], ah[m][1], ah[m][2], ah[m][3], bh[0], bh[1]);
                    MMA(acc[m][2 * np + 1], ah[m][0], ah[m][1], ah[m][2], ah[m][3], bh[2], bh[3]);
                    MMA(acc[m][2 * np],     ah[m][0], ah[m][1], ah[m][2], ah[m][3], bl[0], bl[1]);
                    MMA(acc[m][2 * np + 1], ah[m][0], ah[m][1], ah[m][2], ah[m][3], bl[2], bl[3]);
                    MMA(acc[m][2 * np],     al[m][0], al[m][1], al[m][2], al[m][3], bh[0], bh[1]);
                    MMA(acc[m][2 * np + 1], al[m][0], al[m][1], al[m][2], al[m][3], bh[2], bh[3]);
                }
            }
        }
        __syncthreads();
    }

    // ---- scatter z fragments to padded smem [128][66] fp32 (overlays tiles) ----
    {
        float* zs = (float*)smem;
        const int g = l >> 2, t = l & 3;
#pragma unroll
        for (int m = 0; m < 2; ++m)
#pragma unroll
            for (int nt = 0; nt < 8; ++nt) {
                int tok = w * 32 + m * 16 + g;
                int hcol = nt * 8 + 2 * t;
                *(float2*)(zs + tok * ZSTRIDE + hcol)       = make_float2(acc[m][nt][0], acc[m][nt][1]);
                *(float2*)(zs + (tok + 8) * ZSTRIDE + hcol) = make_float2(acc[m][nt][2], acc[m][nt][3]);
            }
    }
    __syncthreads();

    // ---- RBF epilogue: 1 thread = 1 token; coeff loads are warp-uniform ----
    const float* zrow = (const float*)smem + tid * ZSTRIDE;
    const float4* qs = (const float4*)(smem + OFF_Q);
    float sc = 0.f;
#pragma unroll 1
    for (int h = 0; h < NH; ++h) {
        const float zh = zrow[h];
        const float4* qh = qs + h * NB;
#pragma unroll 16
        for (int k = 0; k < NB; ++k) {
            float4 q = qh[k];
            float p = fmaf(fmaf(q.x, zh, q.y), zh, q.z);
            float e;
            asm("ex2.approx.f32 %0, %1;" : "=f"(e) : "f"(p));
            sc = fmaf(e, q.w, sc);
        }
    }
    out[tok0 + tid] = sc + __ldg(out_bias);
}

extern "C" void kernel_launch(void* const* d_in, const int* in_sizes, int n_in,
                              void* d_out, int out_size)
{
    const float* x          = (const float*)d_in[0];
    const float* in_w       = (const float*)d_in[1];
    const float* in_b       = (const float*)d_in[2];
    const float* centers    = (const float*)d_in[3];
    const float* log_widths = (const float*)d_in[4];
    const float* out_weight = (const float*)d_in[5];
    const float* out_bias   = (const float*)d_in[6];
    float* out = (float*)d_out;

    int ntok = in_sizes[0] / DIMC;          // 65536
    int grid = ntok / MTILE;                // 512

    rbf_prep_kernel<<<(NH * NB + 127) / 128, 128>>>(in_b, centers, log_widths, out_weight);

    cudaFuncSetAttribute(rbf_main_kernel,
                         cudaFuncAttributeMaxDynamicSharedMemorySize, SMEM_TOTAL);
    rbf_main_kernel<<<grid, NTHREADS, SMEM_TOTAL>>>(x, in_w, out_bias, out);
}

// round 4
// speedup vs baseline: 2.0379x; 1.1371x over previous
#include <cuda_runtime.h>
#include <cstdint>

#define NT1      256
#define MTILE    128
#define NCHUNKS  16
#define NH       64
#define NB       64
#define DIMC     1024
#define NTOK     65536

// kernel1 smem: bf16 tiles
#define OFF_AHI  0
#define OFF_ALO  16384
#define OFF_BHI  32768
#define OFF_BLO  40960
#define SMEM_K1  49152

#define NT2      256
#define SMEM_K2  65536   // coeff table

__device__ float  g_z[NH * NTOK];      // z transposed [h][tok], 16 MB
__device__ float4 g_q[NH * NB];        // {s, -2sc', sc'^2, ow}

static __device__ __forceinline__ uint32_t smem_u32(const void* p) {
    uint32_t a;
    asm("{ .reg .u64 t; cvta.to.shared.u64 t, %1; cvt.u32.u64 %0, t; }" : "=r"(a) : "l"(p));
    return a;
}

static __device__ __forceinline__ void split_store(float4 v, uint32_t ahi, uint32_t alo) {
    uint32_t u0 = __float_as_uint(v.x), u1 = __float_as_uint(v.y);
    uint32_t u2 = __float_as_uint(v.z), u3 = __float_as_uint(v.w);
    uint32_t hi01 = __byte_perm(u0, u1, 0x7632);
    uint32_t hi23 = __byte_perm(u2, u3, 0x7632);
    float l0 = v.x - __uint_as_float(u0 & 0xffff0000u);
    float l1 = v.y - __uint_as_float(u1 & 0xffff0000u);
    float l2 = v.z - __uint_as_float(u2 & 0xffff0000u);
    float l3 = v.w - __uint_as_float(u3 & 0xffff0000u);
    uint32_t lo01, lo23;
    asm("cvt.rn.bf16x2.f32 %0, %1, %2;" : "=r"(lo01) : "f"(l1), "f"(l0));
    asm("cvt.rn.bf16x2.f32 %0, %1, %2;" : "=r"(lo23) : "f"(l3), "f"(l2));
    asm volatile("st.shared.v2.b32 [%0], {%1,%2};" :: "r"(ahi), "r"(hi01), "r"(hi23) : "memory");
    asm volatile("st.shared.v2.b32 [%0], {%1,%2};" :: "r"(alo), "r"(lo01), "r"(lo23) : "memory");
}

#define LDSM4(r0, r1, r2, r3, a) \
    asm volatile("ldmatrix.sync.aligned.m8n8.x4.shared.b16 {%0,%1,%2,%3}, [%4];" \
                 : "=r"(r0), "=r"(r1), "=r"(r2), "=r"(r3) : "r"(a))

#define MMA(c, a0, a1, a2, a3, b0, b1) \
    asm volatile("mma.sync.aligned.m16n8k16.row.col.f32.bf16.bf16.f32 " \
                 "{%0,%1,%2,%3}, {%4,%5,%6,%7}, {%8,%9}, {%0,%1,%2,%3};" \
                 : "+f"((c)[0]), "+f"((c)[1]), "+f"((c)[2]), "+f"((c)[3]) \
                 : "r"(a0), "r"(a1), "r"(a2), "r"(a3), "r"(b0), "r"(b1))

// ---- prep: RBF coeff table ----
__global__ void rbf_prep_kernel(const float* __restrict__ in_b,
                                const float* __restrict__ centers,
                                const float* __restrict__ log_widths,
                                const float* __restrict__ out_weight)
{
    int i = blockIdx.x * blockDim.x + threadIdx.x;
    if (i >= NH * NB) return;
    int h = i >> 6;
    float lw = log_widths[i];
    float sp = (lw > 15.f) ? lw : log1pf(expf(lw));
    float w = sp + 0.001f;
    float s = -1.4426950408889634f / (w * w);
    float c = centers[i] - in_b[h];
    float4 q;
    q.x = s; q.y = -2.f * s * c; q.z = s * c * c; q.w = out_weight[i];
    g_q[i] = q;
}

// ---- kernel 1: GEMM z = x @ W^T (bf16 3-term split), z stored [h][tok] ----
__global__ void __launch_bounds__(NT1, 2)
rbf_gemm_kernel(const float* __restrict__ x,
                const float* __restrict__ in_w)
{
    extern __shared__ char smem[];
    const uint32_t sb = smem_u32(smem);
    const int tid = threadIdx.x;
    const int wid = tid >> 5;
    const int l   = tid & 31;
    const int wq  = wid & 3;          // token quarter (32 tok)
    const int wh  = wid >> 2;         // h half (32 h)
    const int tok0 = blockIdx.x * MTILE;

    // staging constants
    const int r0  = tid >> 4;         // 0..15
    const int c4  = tid & 15;
    const uint32_t stc = (uint32_t)c4 * 8u;

    // ldmatrix constants
    const uint32_t key  = (uint32_t)(l & 7);
    const uint32_t rowA = (uint32_t)(wq * 32 + (l & 15));
    const uint32_t chA  = (uint32_t)((l >> 4) & 1);
    const uint32_t rowB = (uint32_t)(wh * 32 + ((l >> 4) << 3) + (l & 7));
    const uint32_t chB  = (uint32_t)((l >> 3) & 1);

    float acc[2][4][4];
#pragma unroll
    for (int m = 0; m < 2; ++m)
#pragma unroll
        for (int nt = 0; nt < 4; ++nt)
#pragma unroll
            for (int j = 0; j < 4; ++j) acc[m][nt][j] = 0.f;

    const float4* xg = (const float4*)x;
    const float4* wg = (const float4*)in_w;

#pragma unroll 1
    for (int ch = 0; ch < NCHUNKS; ++ch) {
        // A: 128 tok x 64 k
#pragma unroll
        for (int it = 0; it < 8; ++it) {
            int row = r0 + it * 16;
            float4 v = xg[(long)(tok0 + row) * 256 + ch * 16 + c4];
            uint32_t sw = ((uint32_t)row * 128u + stc) ^ ((uint32_t)(row & 7) << 4);
            split_store(v, sb + OFF_AHI + sw, sb + OFF_ALO + sw);
        }
        // B: 64 h x 64 k
#pragma unroll
        for (int it = 0; it < 4; ++it) {
            int row = r0 + it * 16;
            float4 v = wg[(long)row * 256 + ch * 16 + c4];
            uint32_t sw = ((uint32_t)row * 128u + stc) ^ ((uint32_t)(row & 7) << 4);
            split_store(v, sb + OFF_BHI + sw, sb + OFF_BLO + sw);
        }
        __syncthreads();

#pragma unroll
        for (int s = 0; s < 4; ++s) {
            const uint32_t colA = ((uint32_t)(s * 2) + chA) ^ key;
            const uint32_t colB = ((uint32_t)(s * 2) + chB) ^ key;
            uint32_t ah[2][4], al[2][4];
#pragma unroll
            for (int m = 0; m < 2; ++m) {
                uint32_t ra = (rowA + m * 16) * 128u + (colA << 4);
                LDSM4(ah[m][0], ah[m][1], ah[m][2], ah[m][3], sb + OFF_AHI + ra);
                LDSM4(al[m][0], al[m][1], al[m][2], al[m][3], sb + OFF_ALO + ra);
            }
#pragma unroll
            for (int np = 0; np < 2; ++np) {
                uint32_t rb = (rowB + np * 16) * 128u + (colB << 4);
                uint32_t bh[4], bl[4];
                LDSM4(bh[0], bh[1], bh[2], bh[3], sb + OFF_BHI + rb);
                LDSM4(bl[0], bl[1], bl[2], bl[3], sb + OFF_BLO + rb);
#pragma unroll
                for (int m = 0; m < 2; ++m) {
                    MMA(acc[m][2 * np],     ah[m][0], ah[m][1], ah[m][2], ah[m][3], bh[0], bh[1]);
                    MMA(acc[m][2 * np + 1], ah[m][0], ah[m][1], ah[m][2], ah[m][3], bh[2], bh[3]);
                    MMA(acc[m][2 * np],     ah[m][0], ah[m][1], ah[m][2], ah[m][3], bl[0], bl[1]);
                    MMA(acc[m][2 * np + 1], ah[m][0], ah[m][1], ah[m][2], ah[m][3], bl[2], bl[3]);
                    MMA(acc[m][2 * np],     al[m][0], al[m][1], al[m][2], al[m][3], bh[0], bh[1]);
                    MMA(acc[m][2 * np + 1], al[m][0], al[m][1], al[m][2], al[m][3], bh[2], bh[3]);
                }
            }
        }
        __syncthreads();
    }

    // ---- write z transposed: g_z[h][tok] ----
    {
        const int g = l >> 2, t = l & 3;
#pragma unroll
        for (int m = 0; m < 2; ++m)
#pragma unroll
            for (int nt = 0; nt < 4; ++nt) {
                int tok = tok0 + wq * 32 + m * 16 + g;
                int h   = wh * 32 + nt * 8 + 2 * t;
                g_z[(long)h * NTOK + tok]             = acc[m][nt][0];
                g_z[(long)(h + 1) * NTOK + tok]       = acc[m][nt][1];
                g_z[(long)h * NTOK + tok + 8]         = acc[m][nt][2];
                g_z[(long)(h + 1) * NTOK + tok + 8]   = acc[m][nt][3];
            }
    }
}

// ---- kernel 2: RBF epilogue, 1 thread = 1 token ----
__global__ void __launch_bounds__(NT2)
rbf_epi_kernel(const float* __restrict__ out_bias, float* __restrict__ out)
{
    extern __shared__ char smem[];
    const int tid = threadIdx.x;
    const int tok = blockIdx.x * NT2 + tid;

    // stage coeff table
    float4* qs = (float4*)smem;
    {
        const float4* gq = g_q;
#pragma unroll
        for (int i = 0; i < 16; ++i) qs[i * NT2 + tid] = gq[i * NT2 + tid];
    }
    __syncthreads();

    float sc = 0.f;
#pragma unroll 1
    for (int h = 0; h < NH; ++h) {
        const float zh = g_z[(long)h * NTOK + tok];
        const float4* qh = qs + h * NB;
#pragma unroll 16
        for (int k = 0; k < NB; ++k) {
            float4 q = qh[k];
            float p = fmaf(fmaf(q.x, zh, q.y), zh, q.z);
            float e;
            asm("ex2.approx.f32 %0, %1;" : "=f"(e) : "f"(p));
            sc = fmaf(e, q.w, sc);
        }
    }
    out[tok] = sc + __ldg(out_bias);
}

extern "C" void kernel_launch(void* const* d_in, const int* in_sizes, int n_in,
                              void* d_out, int out_size)
{
    const float* x          = (const float*)d_in[0];
    const float* in_w       = (const float*)d_in[1];
    const float* in_b       = (const float*)d_in[2];
    const float* centers    = (const float*)d_in[3];
    const float* log_widths = (const float*)d_in[4];
    const float* out_weight = (const float*)d_in[5];
    const float* out_bias   = (const float*)d_in[6];
    float* out = (float*)d_out;

    int ntok = in_sizes[0] / DIMC;          // 65536

    rbf_prep_kernel<<<(NH * NB + 127) / 128, 128>>>(in_b, centers, log_widths, out_weight);

    cudaFuncSetAttribute(rbf_gemm_kernel,
                         cudaFuncAttributeMaxDynamicSharedMemorySize, SMEM_K1);
    rbf_gemm_kernel<<<ntok / MTILE, NT1, SMEM_K1>>>(x, in_w);

    cudaFuncSetAttribute(rbf_epi_kernel,
                         cudaFuncAttributeMaxDynamicSharedMemorySize, SMEM_K2);
    rbf_epi_kernel<<<ntok / NT2, NT2, SMEM_K2>>>(out_bias, out);
}

// round 5
// speedup vs baseline: 2.2005x; 1.0798x over previous
#include <cuda_runtime.h>
#include <cstdint>

#define NT1      256
#define MTILE    128
#define NCHUNKS  16
#define NH       64
#define NB       64
#define DIMC     1024
#define NTOK     65536

// GEMM smem
#define OFF_AHI  0
#define OFF_ALO  16384
#define OFF_BHI  32768
#define OFF_BLO  40960
#define SMEM_K1  49152

#define NT2      256
#define SMEM_FB  65536                 // fallback coeff table
// fast epi smem: owt[64][64] + p1[64] + p2[64]
#define OFF_OWT  0
#define OFF_P1   16384
#define OFF_P2   17408
#define SMEM_EF  18432

__device__ float  g_z[NH * NTOK];      // z transposed [h][tok]
__device__ float4 g_q[NH * NB];        // fallback: {s, -2sc', sc'^2, ow}
__device__ float4 g_p1[NH];            // {c0', sq, d, A}
__device__ float4 g_p2[NH];            // {B, 2B, t=2^{2B}, 0}
__device__ int    g_flag;

static __device__ __forceinline__ uint32_t smem_u32(const void* p) {
    uint32_t a;
    asm("{ .reg .u64 t; cvta.to.shared.u64 t, %1; cvt.u32.u64 %0, t; }" : "=r"(a) : "l"(p));
    return a;
}

#define FMA2(acc, a, b) asm("fma.rn.f32x2 %0, %1, %2, %0;" : "+l"(acc) : "l"(a), "l"(b))
#define MUL2(d, a, b)   asm("mul.rn.f32x2 %0, %1, %2;" : "=l"(d) : "l"(a), "l"(b))
#define PACK2(d, lo, hi) asm("mov.b64 %0, {%1, %2};" : "=l"(d) : "f"(lo), "f"(hi))

static __device__ __forceinline__ void split_store(float4 v, uint32_t ahi, uint32_t alo) {
    uint32_t u0 = __float_as_uint(v.x), u1 = __float_as_uint(v.y);
    uint32_t u2 = __float_as_uint(v.z), u3 = __float_as_uint(v.w);
    uint32_t hi01 = __byte_perm(u0, u1, 0x7632);
    uint32_t hi23 = __byte_perm(u2, u3, 0x7632);
    float l0 = v.x - __uint_as_float(u0 & 0xffff0000u);
    float l1 = v.y - __uint_as_float(u1 & 0xffff0000u);
    float l2 = v.z - __uint_as_float(u2 & 0xffff0000u);
    float l3 = v.w - __uint_as_float(u3 & 0xffff0000u);
    uint32_t lo01, lo23;
    asm("cvt.rn.bf16x2.f32 %0, %1, %2;" : "=r"(lo01) : "f"(l1), "f"(l0));
    asm("cvt.rn.bf16x2.f32 %0, %1, %2;" : "=r"(lo23) : "f"(l3), "f"(l2));
    asm volatile("st.shared.v2.b32 [%0], {%1,%2};" :: "r"(ahi), "r"(hi01), "r"(hi23) : "memory");
    asm volatile("st.shared.v2.b32 [%0], {%1,%2};" :: "r"(alo), "r"(lo01), "r"(lo23) : "memory");
}

#define LDSM4(r0, r1, r2, r3, a) \
    asm volatile("ldmatrix.sync.aligned.m8n8.x4.shared.b16 {%0,%1,%2,%3}, [%4];" \
                 : "=r"(r0), "=r"(r1), "=r"(r2), "=r"(r3) : "r"(a))

#define MMA(c, a0, a1, a2, a3, b0, b1) \
    asm volatile("mma.sync.aligned.m16n8k16.row.col.f32.bf16.bf16.f32 " \
                 "{%0,%1,%2,%3}, {%4,%5,%6,%7}, {%8,%9}, {%0,%1,%2,%3};" \
                 : "+f"((c)[0]), "+f"((c)[1]), "+f"((c)[2]), "+f"((c)[3]) \
                 : "r"(a0), "r"(a1), "r"(a2), "r"(a3), "r"(b0), "r"(b1))

// ---- prep: coeff table + recurrence params + structure check (1 block) ----
__global__ void rbf_prep_kernel(const float* __restrict__ in_b,
                                const float* __restrict__ centers,
                                const float* __restrict__ log_widths,
                                const float* __restrict__ out_weight)
{
    __shared__ int s_ok;
    const int tid = threadIdx.x;
    if (tid == 0) s_ok = 1;
    __syncthreads();

    // fallback coeff table
    for (int i = tid; i < NH * NB; i += blockDim.x) {
        int h = i >> 6;
        float lw = log_widths[i];
        float sp = (lw > 15.f) ? lw : log1pf(expf(lw));
        float w = sp + 0.001f;
        float s = -1.4426950408889634f / (w * w);
        float c = centers[i] - in_b[h];
        float4 q;
        q.x = s; q.y = -2.f * s * c; q.z = s * c * c; q.w = out_weight[i];
        g_q[i] = q;
    }

    // per-h recurrence params + structure validation
    if (tid < NH) {
        int h = tid;
        float c0 = centers[h * NB];
        float d  = (centers[h * NB + NB - 1] - c0) / (float)(NB - 1);
        float lw0 = log_widths[h * NB];
        bool ok = true;
        for (int k = 0; k < NB; ++k) {
            ok &= fabsf(centers[h * NB + k] - (c0 + (float)k * d)) <= 1e-5f;
            ok &= fabsf(log_widths[h * NB + k] - lw0) <= 1e-6f;
        }
        if (!ok) atomicAnd(&s_ok, 0);
        float sp = (lw0 > 15.f) ? lw0 : log1pf(expf(lw0));
        float w  = sp + 0.001f;
        float sq = -1.4426950408889634f / (w * w);     // -log2e / w^2
        float A  = -2.f * sq * d;
        float B  = sq * d * d;
        float4 p1, p2;
        p1.x = c0 - in_b[h]; p1.y = sq; p1.z = d; p1.w = A;
        p2.x = B; p2.y = 2.f * B; p2.z = exp2f(2.f * B); p2.w = 0.f;
        g_p1[h] = p1; g_p2[h] = p2;
    }
    __syncthreads();
    if (tid == 0) g_flag = s_ok;
}

// ---- kernel 1: GEMM z = x @ W^T (bf16 3-term split), z stored [h][tok] ----
__global__ void __launch_bounds__(NT1, 2)
rbf_gemm_kernel(const float* __restrict__ x,
                const float* __restrict__ in_w)
{
    extern __shared__ char smem[];
    const uint32_t sb = smem_u32(smem);
    const int tid = threadIdx.x;
    const int wid = tid >> 5;
    const int l   = tid & 31;
    const int wq  = wid & 3;
    const int wh  = wid >> 2;
    const int tok0 = blockIdx.x * MTILE;

    const int r0  = tid >> 4;
    const int c4  = tid & 15;
    const uint32_t stc = (uint32_t)c4 * 8u;

    const uint32_t key  = (uint32_t)(l & 7);
    const uint32_t rowA = (uint32_t)(wq * 32 + (l & 15));
    const uint32_t chA  = (uint32_t)((l >> 4) & 1);
    const uint32_t rowB = (uint32_t)(wh * 32 + ((l >> 4) << 3) + (l & 7));
    const uint32_t chB  = (uint32_t)((l >> 3) & 1);

    float acc[2][4][4];
#pragma unroll
    for (int m = 0; m < 2; ++m)
#pragma unroll
        for (int nt = 0; nt < 4; ++nt)
#pragma unroll
            for (int j = 0; j < 4; ++j) acc[m][nt][j] = 0.f;

    const float4* xg = (const float4*)x;
    const float4* wg = (const float4*)in_w;

#pragma unroll 1
    for (int ch = 0; ch < NCHUNKS; ++ch) {
#pragma unroll
        for (int it = 0; it < 8; ++it) {
            int row = r0 + it * 16;
            float4 v = xg[(long)(tok0 + row) * 256 + ch * 16 + c4];
            uint32_t sw = ((uint32_t)row * 128u + stc) ^ ((uint32_t)(row & 7) << 4);
            split_store(v, sb + OFF_AHI + sw, sb + OFF_ALO + sw);
        }
#pragma unroll
        for (int it = 0; it < 4; ++it) {
            int row = r0 + it * 16;
            float4 v = wg[(long)row * 256 + ch * 16 + c4];
            uint32_t sw = ((uint32_t)row * 128u + stc) ^ ((uint32_t)(row & 7) << 4);
            split_store(v, sb + OFF_BHI + sw, sb + OFF_BLO + sw);
        }
        __syncthreads();

#pragma unroll
        for (int s = 0; s < 4; ++s) {
            const uint32_t colA = ((uint32_t)(s * 2) + chA) ^ key;
            const uint32_t colB = ((uint32_t)(s * 2) + chB) ^ key;
            uint32_t ah[2][4], al[2][4];
#pragma unroll
            for (int m = 0; m < 2; ++m) {
                uint32_t ra = (rowA + m * 16) * 128u + (colA << 4);
                LDSM4(ah[m][0], ah[m][1], ah[m][2], ah[m][3], sb + OFF_AHI + ra);
                LDSM4(al[m][0], al[m][1], al[m][2], al[m][3], sb + OFF_ALO + ra);
            }
#pragma unroll
            for (int np = 0; np < 2; ++np) {
                uint32_t rb = (rowB + np * 16) * 128u + (colB << 4);
                uint32_t bh[4], bl[4];
                LDSM4(bh[0], bh[1], bh[2], bh[3], sb + OFF_BHI + rb);
                LDSM4(bl[0], bl[1], bl[2], bl[3], sb + OFF_BLO + rb);
#pragma unroll
                for (int m = 0; m < 2; ++m) {
                    MMA(acc[m][2 * np],     ah[m][0], ah[m][1], ah[m][2], ah[m][3], bh[0], bh[1]);
                    MMA(acc[m][2 * np + 1], ah[m][0], ah[m][1], ah[m][2], ah[m][3], bh[2], bh[3]);
                    MMA(acc[m][2 * np],     ah[m][0], ah[m][1], ah[m][2], ah[m][3], bl[0], bl[1]);
                    MMA(acc[m][2 * np + 1], ah[m][0], ah[m][1], ah[m][2], ah[m][3], bl[2], bl[3]);
                    MMA(acc[m][2 * np],     al[m][0], al[m][1], al[m][2], al[m][3], bh[0], bh[1]);
                    MMA(acc[m][2 * np + 1], al[m][0], al[m][1], al[m][2], al[m][3], bh[2], bh[3]);
                }
            }
        }
        __syncthreads();
    }

    {
        const int g = l >> 2, t = l & 3;
#pragma unroll
        for (int m = 0; m < 2; ++m)
#pragma unroll
            for (int nt = 0; nt < 4; ++nt) {
                int tok = tok0 + wq * 32 + m * 16 + g;
                int h   = wh * 32 + nt * 8 + 2 * t;
                g_z[(long)h * NTOK + tok]           = acc[m][nt][0];
                g_z[(long)(h + 1) * NTOK + tok]     = acc[m][nt][1];
                g_z[(long)h * NTOK + tok + 8]       = acc[m][nt][2];
                g_z[(long)(h + 1) * NTOK + tok + 8] = acc[m][nt][3];
            }
    }
}

// ---- kernel 2a: fast epilogue (geometric recurrence, f32x2-packed) ----
__global__ void __launch_bounds__(NT2)
rbf_epi_fast(const float* __restrict__ out_weight,
             const float* __restrict__ out_bias,
             float* __restrict__ out)
{
    if (!g_flag) return;
    extern __shared__ char smem[];
    const uint32_t sb = smem_u32(smem);
    const int tid = threadIdx.x;
    const int tok = blockIdx.x * NT2 + tid;

    // stage out_weight transposed: owt[k][h]
    {
        float* owt = (float*)(smem + OFF_OWT);
#pragma unroll
        for (int j = 0; j < 16; ++j) {
            int i = j * NT2 + tid;                // dest index: k*64 + h
            owt[i] = out_weight[((i & 63) << 6) + (i >> 6)];
        }
        if (tid < NH) {
            ((float4*)(smem + OFF_P1))[tid] = g_p1[tid];
            ((float4*)(smem + OFF_P2))[tid] = g_p2[tid];
        }
    }
    __syncthreads();

    const float4* p1s = (const float4*)(smem + OFF_P1);
    const float4* p2s = (const float4*)(smem + OFF_P2);

    unsigned long long acc2 = 0ull;
#pragma unroll 1
    for (int hp = 0; hp < NH / 2; ++hp) {
        const int h0 = 2 * hp;
        float z0 = g_z[(long)h0 * NTOK + tok];
        float z1 = g_z[(long)(h0 + 1) * NTOK + tok];
        float4 Pa = p1s[h0], Pb = p1s[h0 + 1];
        float4 Qa = p2s[h0], Qb = p2s[h0 + 1];
        float u0 = z0 - Pa.x, u1 = z1 - Pb.x;
        float rb0 = fmaf(Pa.w, u0, Qa.x);
        float rb1 = fmaf(Pb.w, u1, Qb.x);
        unsigned long long tt;
        PACK2(tt, Qa.z, Qb.z);
        const uint32_t owbase = sb + OFF_OWT + (uint32_t)hp * 8u;
#pragma unroll
        for (int m = 0; m < 4; ++m) {
            const float km = (float)(16 * m);
            float v0 = fmaf(-km, Pa.z, u0);
            float v1 = fmaf(-km, Pb.z, u1);
            float e0, e1, r0, r1;
            float a0 = Pa.y * v0 * v0, a1 = Pb.y * v1 * v1;
            asm("ex2.approx.f32 %0, %1;" : "=f"(e0) : "f"(a0));
            asm("ex2.approx.f32 %0, %1;" : "=f"(e1) : "f"(a1));
            float b0 = fmaf(km, Qa.y, rb0), b1 = fmaf(km, Qb.y, rb1);
            asm("ex2.approx.f32 %0, %1;" : "=f"(r0) : "f"(b0));
            asm("ex2.approx.f32 %0, %1;" : "=f"(r1) : "f"(b1));
            unsigned long long e01, r01;
            PACK2(e01, e0, e1);
            PACK2(r01, r0, r1);
            uint32_t a = owbase + (uint32_t)m * (16u * 256u);
#pragma unroll
            for (int kk = 0; kk < 16; ++kk) {
                unsigned long long w2;
                asm volatile("ld.shared.b64 %0, [%1];" : "=l"(w2) : "r"(a));
                a += 256u;
                FMA2(acc2, e01, w2);
                MUL2(e01, e01, r01);
                MUL2(r01, r01, tt);
            }
        }
    }
    float lo, hi;
    asm("mov.b64 {%0,%1}, %2;" : "=f"(lo), "=f"(hi) : "l"(acc2));
    out[tok] = lo + hi + __ldg(out_bias);
}

// ---- kernel 2b: fallback epilogue (general, ex2 per term) ----
__global__ void __launch_bounds__(NT2)
rbf_epi_fallback(const float* __restrict__ out_bias, float* __restrict__ out)
{
    if (g_flag) return;
    extern __shared__ char smem[];
    const int tid = threadIdx.x;
    const int tok = blockIdx.x * NT2 + tid;

    float4* qs = (float4*)smem;
    {
        const float4* gq = g_q;
#pragma unroll
        for (int i = 0; i < 16; ++i) qs[i * NT2 + tid] = gq[i * NT2 + tid];
    }
    __syncthreads();

    float sc = 0.f;
#pragma unroll 1
    for (int h = 0; h < NH; ++h) {
        const float zh = g_z[(long)h * NTOK + tok];
        const float4* qh = qs + h * NB;
#pragma unroll 16
        for (int k = 0; k < NB; ++k) {
            float4 q = qh[k];
            float p = fmaf(fmaf(q.x, zh, q.y), zh, q.z);
            float e;
            asm("ex2.approx.f32 %0, %1;" : "=f"(e) : "f"(p));
            sc = fmaf(e, q.w, sc);
        }
    }
    out[tok] = sc + __ldg(out_bias);
}

extern "C" void kernel_launch(void* const* d_in, const int* in_sizes, int n_in,
                              void* d_out, int out_size)
{
    const float* x          = (const float*)d_in[0];
    const float* in_w       = (const float*)d_in[1];
    const float* in_b       = (const float*)d_in[2];
    const float* centers    = (const float*)d_in[3];
    const float* log_widths = (const float*)d_in[4];
    const float* out_weight = (const float*)d_in[5];
    const float* out_bias   = (const float*)d_in[6];
    float* out = (float*)d_out;

    int ntok = in_sizes[0] / DIMC;          // 65536

    rbf_prep_kernel<<<1, 256>>>(in_b, centers, log_widths, out_weight);

    cudaFuncSetAttribute(rbf_gemm_kernel,
                         cudaFuncAttributeMaxDynamicSharedMemorySize, SMEM_K1);
    rbf_gemm_kernel<<<ntok / MTILE, NT1, SMEM_K1>>>(x, in_w);

    cudaFuncSetAttribute(rbf_epi_fast,
                         cudaFuncAttributeMaxDynamicSharedMemorySize, SMEM_EF);
    rbf_epi_fast<<<ntok / NT2, NT2, SMEM_EF>>>(out_weight, out_bias, out);

    cudaFuncSetAttribute(rbf_epi_fallback,
                         cudaFuncAttributeMaxDynamicSharedMemorySize, SMEM_FB);
    rbf_epi_fallback<<<ntok / NT2, NT2, SMEM_FB>>>(out_bias, out);
}

// round 6
// speedup vs baseline: 2.5888x; 1.1765x over previous
#include <cuda_runtime.h>
#include <cstdint>

#define NT1      256
#define MTILE    128
#define NCHUNKS  16
#define NH       64
#define NB       64
#define DIMC     1024

// stage layout (two stages)
#define STAGE_BYTES 49152
#define OFF_AHI  0
#define OFF_ALO  16384
#define OFF_BHI  32768
#define OFF_BLO  40960
// post-GEMM overlay
#define OFF_ZS   0                    // float[128*66] = 33792 B
#define OFF_OWT  34816                // float[64*64]  = 16384 B
#define OFF_P1   51200                // float4[64]
#define OFF_P2   52224                // float4[64]
#define SMEM_TOTAL (2 * STAGE_BYTES)  // 98304

__device__ float4 g_q[NH * NB];        // fallback coeffs {s, -2sc', sc'^2, ow}
__device__ float  g_owt[NH * NB];      // out_weight transposed [k][h]
__device__ float4 g_p1[NH];            // {c0', sq, d, A}
__device__ float4 g_p2[NH];            // {B, 2B, 2^{2B}, 0}
__device__ int    g_flag;

static __device__ __forceinline__ uint32_t smem_u32(const void* p) {
    uint32_t a;
    asm("{ .reg .u64 t; cvta.to.shared.u64 t, %1; cvt.u32.u64 %0, t; }" : "=r"(a) : "l"(p));
    return a;
}

#define FMA2(acc, a, b) asm("fma.rn.f32x2 %0, %1, %2, %0;" : "+l"(acc) : "l"(a), "l"(b))
#define MUL2(d, a, b)   asm("mul.rn.f32x2 %0, %1, %2;" : "=l"(d) : "l"(a), "l"(b))
#define PACK2(d, lo, hi) asm("mov.b64 %0, {%1, %2};" : "=l"(d) : "f"(lo), "f"(hi))

static __device__ __forceinline__ void split_store(float4 v, uint32_t ahi, uint32_t alo) {
    uint32_t u0 = __float_as_uint(v.x), u1 = __float_as_uint(v.y);
    uint32_t u2 = __float_as_uint(v.z), u3 = __float_as_uint(v.w);
    uint32_t hi01 = __byte_perm(u0, u1, 0x7632);
    uint32_t hi23 = __byte_perm(u2, u3, 0x7632);
    float l0 = v.x - __uint_as_float(u0 & 0xffff0000u);
    float l1 = v.y - __uint_as_float(u1 & 0xffff0000u);
    float l2 = v.z - __uint_as_float(u2 & 0xffff0000u);
    float l3 = v.w - __uint_as_float(u3 & 0xffff0000u);
    uint32_t lo01, lo23;
    asm("cvt.rn.bf16x2.f32 %0, %1, %2;" : "=r"(lo01) : "f"(l1), "f"(l0));
    asm("cvt.rn.bf16x2.f32 %0, %1, %2;" : "=r"(lo23) : "f"(l3), "f"(l2));
    asm volatile("st.shared.v2.b32 [%0], {%1,%2};" :: "r"(ahi), "r"(hi01), "r"(hi23) : "memory");
    asm volatile("st.shared.v2.b32 [%0], {%1,%2};" :: "r"(alo), "r"(lo01), "r"(lo23) : "memory");
}

#define LDSM4(r0, r1, r2, r3, a) \
    asm volatile("ldmatrix.sync.aligned.m8n8.x4.shared.b16 {%0,%1,%2,%3}, [%4];" \
                 : "=r"(r0), "=r"(r1), "=r"(r2), "=r"(r3) : "r"(a))

#define MMA(c, a0, a1, a2, a3, b0, b1) \
    asm volatile("mma.sync.aligned.m16n8k16.row.col.f32.bf16.bf16.f32 " \
                 "{%0,%1,%2,%3}, {%4,%5,%6,%7}, {%8,%9}, {%0,%1,%2,%3};" \
                 : "+f"((c)[0]), "+f"((c)[1]), "+f"((c)[2]), "+f"((c)[3]) \
                 : "r"(a0), "r"(a1), "r"(a2), "r"(a3), "r"(b0), "r"(b1))

// ---- prep: tables + recurrence params + structure check ----
__global__ void rbf_prep_kernel(const float* __restrict__ in_b,
                                const float* __restrict__ centers,
                                const float* __restrict__ log_widths,
                                const float* __restrict__ out_weight)
{
    __shared__ int s_ok;
    const int tid = threadIdx.x;
    if (tid == 0) s_ok = 1;
    __syncthreads();

    for (int i = tid; i < NH * NB; i += blockDim.x) {
        int h = i >> 6;
        float lw = log_widths[i];
        float sp = (lw > 15.f) ? lw : log1pf(expf(lw));
        float w = sp + 0.001f;
        float s = -1.4426950408889634f / (w * w);
        float c = centers[i] - in_b[h];
        float4 q;
        q.x = s; q.y = -2.f * s * c; q.z = s * c * c; q.w = out_weight[i];
        g_q[i] = q;
        g_owt[i] = out_weight[((i & 63) << 6) + (i >> 6)];   // [k][h]
    }

    if (tid < NH) {
        int h = tid;
        float c0 = centers[h * NB];
        float d  = (centers[h * NB + NB - 1] - c0) / (float)(NB - 1);
        float lw0 = log_widths[h * NB];
        bool ok = true;
        for (int k = 0; k < NB; ++k) {
            ok &= fabsf(centers[h * NB + k] - (c0 + (float)k * d)) <= 1e-5f;
            ok &= fabsf(log_widths[h * NB + k] - lw0) <= 1e-6f;
        }
        if (!ok) atomicAnd(&s_ok, 0);
        float sp = (lw0 > 15.f) ? lw0 : log1pf(expf(lw0));
        float w  = sp + 0.001f;
        float sq = -1.4426950408889634f / (w * w);
        float A  = -2.f * sq * d;
        float B  = sq * d * d;
        float4 p1, p2;
        p1.x = c0 - in_b[h]; p1.y = sq; p1.z = d; p1.w = A;
        p2.x = B; p2.y = 2.f * B; p2.z = exp2f(2.f * B); p2.w = 0.f;
        g_p1[h] = p1; g_p2[h] = p2;
    }
    __syncthreads();
    if (tid == 0) g_flag = s_ok;
}

// ---- fused GEMM + RBF kernel ----
__global__ void __launch_bounds__(NT1, 2)
rbf_fused_kernel(const float* __restrict__ x,
                 const float* __restrict__ in_w,
                 const float* __restrict__ out_bias,
                 float* __restrict__ out)
{
    extern __shared__ char smem[];
    const uint32_t sb = smem_u32(smem);
    const int tid = threadIdx.x;
    const int wid = tid >> 5;
    const int l   = tid & 31;
    const int wq  = wid & 3;
    const int wh  = wid >> 2;
    const int tok0 = blockIdx.x * MTILE;

    const int r0  = tid >> 4;
    const int c4  = tid & 15;
    const uint32_t stc = (uint32_t)c4 * 8u;

    const uint32_t key  = (uint32_t)(l & 7);
    const uint32_t rowA = (uint32_t)(wq * 32 + (l & 15));
    const uint32_t chA  = (uint32_t)((l >> 4) & 1);
    const uint32_t rowB = (uint32_t)(wh * 32 + ((l >> 4) << 3) + (l & 7));
    const uint32_t chB  = (uint32_t)((l >> 3) & 1);

    float acc[2][4][4];
#pragma unroll
    for (int m = 0; m < 2; ++m)
#pragma unroll
        for (int nt = 0; nt < 4; ++nt)
#pragma unroll
            for (int j = 0; j < 4; ++j) acc[m][nt][j] = 0.f;

    const float4* xg = (const float4*)x;
    const float4* wg = (const float4*)in_w;

    float4 pa[8], pb[4];
    // prologue: chunk 0 -> stage 0
#pragma unroll
    for (int it = 0; it < 8; ++it)
        pa[it] = xg[(long)(tok0 + r0 + it * 16) * 256 + c4];
#pragma unroll
    for (int it = 0; it < 4; ++it)
        pb[it] = wg[(long)(r0 + it * 16) * 256 + c4];
#pragma unroll
    for (int it = 0; it < 8; ++it) {
        int row = r0 + it * 16;
        uint32_t sw = ((uint32_t)row * 128u + stc) ^ ((uint32_t)(row & 7) << 4);
        split_store(pa[it], sb + OFF_AHI + sw, sb + OFF_ALO + sw);
    }
#pragma unroll
    for (int it = 0; it < 4; ++it) {
        int row = r0 + it * 16;
        uint32_t sw = ((uint32_t)row * 128u + stc) ^ ((uint32_t)(row & 7) << 4);
        split_store(pb[it], sb + OFF_BHI + sw, sb + OFF_BLO + sw);
    }
    __syncthreads();

#pragma unroll 1
    for (int ch = 0; ch < NCHUNKS; ++ch) {
        const uint32_t sbase = sb + (uint32_t)(ch & 1) * STAGE_BYTES;

        // prefetch next chunk into registers (issue before MMA phase)
        if (ch < NCHUNKS - 1) {
#pragma unroll
            for (int it = 0; it < 8; ++it)
                pa[it] = xg[(long)(tok0 + r0 + it * 16) * 256 + (ch + 1) * 16 + c4];
#pragma unroll
            for (int it = 0; it < 4; ++it)
                pb[it] = wg[(long)(r0 + it * 16) * 256 + (ch + 1) * 16 + c4];
        }

        // MMA phase on current stage
#pragma unroll
        for (int s = 0; s < 4; ++s) {
            const uint32_t colA = ((uint32_t)(s * 2) + chA) ^ key;
            const uint32_t colB = ((uint32_t)(s * 2) + chB) ^ key;
            uint32_t ah[2][4], al[2][4];
#pragma unroll
            for (int m = 0; m < 2; ++m) {
                uint32_t ra = (rowA + m * 16) * 128u + (colA << 4);
                LDSM4(ah[m][0], ah[m][1], ah[m][2], ah[m][3], sbase + OFF_AHI + ra);
                LDSM4(al[m][0], al[m][1], al[m][2], al[m][3], sbase + OFF_ALO + ra);
            }
#pragma unroll
            for (int np = 0; np < 2; ++np) {
                uint32_t rb = (rowB + np * 16) * 128u + (colB << 4);
                uint32_t bh[4], bl[4];
                LDSM4(bh[0], bh[1], bh[2], bh[3], sbase + OFF_BHI + rb);
                LDSM4(bl[0], bl[1], bl[2], bl[3], sbase + OFF_BLO + rb);
#pragma unroll
                for (int m = 0; m < 2; ++m) {
                    MMA(acc[m][2 * np],     ah[m][0], ah[m][1], ah[m][2], ah[m][3], bh[0], bh[1]);
                    MMA(acc[m][2 * np + 1], ah[m][0], ah[m][1], ah[m][2], ah[m][3], bh[2], bh[3]);
                    MMA(acc[m][2 * np],     ah[m][0], ah[m][1], ah[m][2], ah[m][3], bl[0], bl[1]);
                    MMA(acc[m][2 * np + 1], ah[m][0], ah[m][1], ah[m][2], ah[m][3], bl[2], bl[3]);
                    MMA(acc[m][2 * np],     al[m][0], al[m][1], al[m][2], al[m][3], bh[0], bh[1]);
                    MMA(acc[m][2 * np + 1], al[m][0], al[m][1], al[m][2], al[m][3], bh[2], bh[3]);
                }
            }
        }

        // store prefetched chunk into the other stage
        if (ch < NCHUNKS - 1) {
            const uint32_t dbase = sb + (uint32_t)((ch + 1) & 1) * STAGE_BYTES;
#pragma unroll
            for (int it = 0; it < 8; ++it) {
                int row = r0 + it * 16;
                uint32_t sw = ((uint32_t)row * 128u + stc) ^ ((uint32_t)(row & 7) << 4);
                split_store(pa[it], dbase + OFF_AHI + sw, dbase + OFF_ALO + sw);
            }
#pragma unroll
            for (int it = 0; it < 4; ++it) {
                int row = r0 + it * 16;
                uint32_t sw = ((uint32_t)row * 128u + stc) ^ ((uint32_t)(row & 7) << 4);
                split_store(pb[it], dbase + OFF_BHI + sw, dbase + OFF_BLO + sw);
            }
        }
        __syncthreads();
    }

    // ---- overlay: write z to smem [128][66] ----
    {
        float* zs = (float*)(smem + OFF_ZS);
        const int g = l >> 2, t = l & 3;
#pragma unroll
        for (int m = 0; m < 2; ++m)
#pragma unroll
            for (int nt = 0; nt < 4; ++nt) {
                int tok = wq * 32 + m * 16 + g;
                int hcol = wh * 32 + nt * 8 + 2 * t;
                *(float2*)(zs + tok * 66 + hcol)       = make_float2(acc[m][nt][0], acc[m][nt][1]);
                *(float2*)(zs + (tok + 8) * 66 + hcol) = make_float2(acc[m][nt][2], acc[m][nt][3]);
            }
        // stage tables
        float* owt = (float*)(smem + OFF_OWT);
#pragma unroll
        for (int j = 0; j < 16; ++j) owt[j * NT1 + tid] = g_owt[j * NT1 + tid];
        if (tid < NH) {
            ((float4*)(smem + OFF_P1))[tid] = g_p1[tid];
            ((float4*)(smem + OFF_P2))[tid] = g_p2[tid];
        }
    }
    __syncthreads();

    // ---- epilogue: thread = half token (32 h), combine via shuffle ----
    const int tok  = tid >> 1;
    const int half = tid & 1;
    const float* zrow = (const float*)(smem + OFF_ZS) + tok * 66 + half * 32;
    const float4* p1s = (const float4*)(smem + OFF_P1);
    const float4* p2s = (const float4*)(smem + OFF_P2);
    float sum;

    if (g_flag) {
        unsigned long long acc2 = 0ull;
#pragma unroll 1
        for (int hp = 0; hp < 16; ++hp) {
            const int h0 = half * 32 + 2 * hp;
            float2 zz = *(const float2*)(zrow + 2 * hp);
            float4 Pa = p1s[h0], Pb = p1s[h0 + 1];
            float4 Qa = p2s[h0], Qb = p2s[h0 + 1];
            float u0 = zz.x - Pa.x, u1 = zz.y - Pb.x;
            float rb0 = fmaf(Pa.w, u0, Qa.x);
            float rb1 = fmaf(Pb.w, u1, Qb.x);
            unsigned long long tt;
            PACK2(tt, Qa.z, Qb.z);
            const uint32_t owbase = sb + OFF_OWT + (uint32_t)h0 * 4u;
#pragma unroll
            for (int m = 0; m < 4; ++m) {
                const float km = (float)(16 * m);
                float v0 = fmaf(-km, Pa.z, u0);
                float v1 = fmaf(-km, Pb.z, u1);
                float e0, e1, rr0, rr1;
                float a0 = Pa.y * v0 * v0, a1 = Pb.y * v1 * v1;
                asm("ex2.approx.f32 %0, %1;" : "=f"(e0) : "f"(a0));
                asm("ex2.approx.f32 %0, %1;" : "=f"(e1) : "f"(a1));
                float b0 = fmaf(km, Qa.y, rb0), b1 = fmaf(km, Qb.y, rb1);
                asm("ex2.approx.f32 %0, %1;" : "=f"(rr0) : "f"(b0));
                asm("ex2.approx.f32 %0, %1;" : "=f"(rr1) : "f"(b1));
                unsigned long long e01, r01;
                PACK2(e01, e0, e1);
                PACK2(r01, rr0, rr1);
                uint32_t a = owbase + (uint32_t)m * (16u * 256u);
#pragma unroll
                for (int kk = 0; kk < 16; ++kk) {
                    unsigned long long w2;
                    asm volatile("ld.shared.b64 %0, [%1];" : "=l"(w2) : "r"(a));
                    a += 256u;
                    FMA2(acc2, e01, w2);
                    MUL2(e01, e01, r01);
                    MUL2(r01, r01, tt);
                }
            }
        }
        float lo, hi;
        asm("mov.b64 {%0,%1}, %2;" : "=f"(lo), "=f"(hi) : "l"(acc2));
        sum = lo + hi;
    } else {
        // general fallback: coeffs straight from L2
        sum = 0.f;
#pragma unroll 1
        for (int i = 0; i < 32; ++i) {
            const int h = half * 32 + i;
            const float zh = zrow[i];
            const float4* qh = g_q + h * NB;
#pragma unroll 8
            for (int k = 0; k < NB; ++k) {
                float4 q = qh[k];
                float p = fmaf(fmaf(q.x, zh, q.y), zh, q.z);
                float e;
                asm("ex2.approx.f32 %0, %1;" : "=f"(e) : "f"(p));
                sum = fmaf(e, q.w, sum);
            }
        }
    }

    sum += __shfl_xor_sync(0xffffffffu, sum, 1);
    if (half == 0) out[tok0 + tok] = sum + __ldg(out_bias);
}

extern "C" void kernel_launch(void* const* d_in, const int* in_sizes, int n_in,
                              void* d_out, int out_size)
{
    const float* x          = (const float*)d_in[0];
    const float* in_w       = (const float*)d_in[1];
    const float* in_b       = (const float*)d_in[2];
    const float* centers    = (const float*)d_in[3];
    const float* log_widths = (const float*)d_in[4];
    const float* out_weight = (const float*)d_in[5];
    const float* out_bias   = (const float*)d_in[6];
    float* out = (float*)d_out;

    int ntok = in_sizes[0] / DIMC;          // 65536

    rbf_prep_kernel<<<1, 256>>>(in_b, centers, log_widths, out_weight);

    cudaFuncSetAttribute(rbf_fused_kernel,
                         cudaFuncAttributeMaxDynamicSharedMemorySize, SMEM_TOTAL);
    rbf_fused_kernel<<<ntok / MTILE, NT1, SMEM_TOTAL>>>(x, in_w, out_bias, out);
}

// round 7
// speedup vs baseline: 2.6302x; 1.0160x over previous
#include <cuda_runtime.h>
#include <cstdint>

#define NT1      256
#define MTILE    128
#define NCHUNKS  16
#define NH       64
#define NB       64
#define DIMC     1024

// stage layout (two stages)
#define STAGE_BYTES 49152
#define OFF_AHI  0
#define OFF_ALO  16384
#define OFF_BHI  32768          // B hi (8 KB) + B lo (8 KB) contiguous
// post-GEMM overlay
#define OFF_ZS   0              // float[128*66] = 33792 B
#define OFF_OWT  34816          // float[64*64]  = 16384 B
#define OFF_P1   51200
#define OFF_P2   52224
#define SMEM_TOTAL (2 * STAGE_BYTES)

__device__ float4 g_q[NH * NB];
__device__ float  g_owt[NH * NB];          // out_weight transposed [k][h]
__device__ float4 g_p1[NH];                // {c0', sq, d, A}
__device__ float4 g_p2[NH];                // {B, 2B, 2^{2B}, 0}
__device__ int    g_flag;
__device__ __align__(16) unsigned char g_wt[NCHUNKS * 16384];  // pre-split W tiles

static __device__ __forceinline__ uint32_t smem_u32(const void* p) {
    uint32_t a;
    asm("{ .reg .u64 t; cvta.to.shared.u64 t, %1; cvt.u32.u64 %0, t; }" : "=r"(a) : "l"(p));
    return a;
}

#define FMA2(acc, a, b) asm("fma.rn.f32x2 %0, %1, %2, %0;" : "+l"(acc) : "l"(a), "l"(b))
#define MUL2(d, a, b)   asm("mul.rn.f32x2 %0, %1, %2;" : "=l"(d) : "l"(a), "l"(b))
#define PACK2(d, lo, hi) asm("mov.b64 %0, {%1, %2};" : "=l"(d) : "f"(lo), "f"(hi))

#define CP_ASYNC16(dst, src) \
    asm volatile("cp.async.ca.shared.global [%0], [%1], 16;" :: "r"(dst), "l"(src) : "memory")
#define CP_COMMIT() asm volatile("cp.async.commit_group;" ::: "memory")
#define CP_WAIT0()  asm volatile("cp.async.wait_group 0;" ::: "memory")

static __device__ __forceinline__ void split_pack(float4 v, uint32_t& hi01, uint32_t& hi23,
                                                  uint32_t& lo01, uint32_t& lo23) {
    uint32_t u0 = __float_as_uint(v.x), u1 = __float_as_uint(v.y);
    uint32_t u2 = __float_as_uint(v.z), u3 = __float_as_uint(v.w);
    hi01 = __byte_perm(u0, u1, 0x7632);
    hi23 = __byte_perm(u2, u3, 0x7632);
    float l0 = v.x - __uint_as_float(u0 & 0xffff0000u);
    float l1 = v.y - __uint_as_float(u1 & 0xffff0000u);
    float l2 = v.z - __uint_as_float(u2 & 0xffff0000u);
    float l3 = v.w - __uint_as_float(u3 & 0xffff0000u);
    asm("cvt.rn.bf16x2.f32 %0, %1, %2;" : "=r"(lo01) : "f"(l1), "f"(l0));
    asm("cvt.rn.bf16x2.f32 %0, %1, %2;" : "=r"(lo23) : "f"(l3), "f"(l2));
}

static __device__ __forceinline__ void split_store(float4 v, uint32_t ahi, uint32_t alo) {
    uint32_t hi01, hi23, lo01, lo23;
    split_pack(v, hi01, hi23, lo01, lo23);
    asm volatile("st.shared.v2.b32 [%0], {%1,%2};" :: "r"(ahi), "r"(hi01), "r"(hi23) : "memory");
    asm volatile("st.shared.v2.b32 [%0], {%1,%2};" :: "r"(alo), "r"(lo01), "r"(lo23) : "memory");
}

#define LDSM4(r0, r1, r2, r3, a) \
    asm volatile("ldmatrix.sync.aligned.m8n8.x4.shared.b16 {%0,%1,%2,%3}, [%4];" \
                 : "=r"(r0), "=r"(r1), "=r"(r2), "=r"(r3) : "r"(a))

#define MMA(c, a0, a1, a2, a3, b0, b1) \
    asm volatile("mma.sync.aligned.m16n8k16.row.col.f32.bf16.bf16.f32 " \
                 "{%0,%1,%2,%3}, {%4,%5,%6,%7}, {%8,%9}, {%0,%1,%2,%3};" \
                 : "+f"((c)[0]), "+f"((c)[1]), "+f"((c)[2]), "+f"((c)[3]) \
                 : "r"(a0), "r"(a1), "r"(a2), "r"(a3), "r"(b0), "r"(b1))

// ---- prep1: tables + recurrence params + structure check ----
__global__ void rbf_prep1(const float* __restrict__ in_b,
                          const float* __restrict__ centers,
                          const float* __restrict__ log_widths,
                          const float* __restrict__ out_weight)
{
    __shared__ int s_ok;
    const int tid = threadIdx.x;
    if (tid == 0) s_ok = 1;
    __syncthreads();

    for (int i = tid; i < NH * NB; i += blockDim.x) {
        int h = i >> 6;
        float lw = log_widths[i];
        float sp = (lw > 15.f) ? lw : log1pf(expf(lw));
        float w = sp + 0.001f;
        float s = -1.4426950408889634f / (w * w);
        float c = centers[i] - in_b[h];
        float4 q;
        q.x = s; q.y = -2.f * s * c; q.z = s * c * c; q.w = out_weight[i];
        g_q[i] = q;
        g_owt[i] = out_weight[((i & 63) << 6) + (i >> 6)];
    }

    if (tid < NH) {
        int h = tid;
        float c0 = centers[h * NB];
        float d  = (centers[h * NB + NB - 1] - c0) / (float)(NB - 1);
        float lw0 = log_widths[h * NB];
        bool ok = true;
        for (int k = 0; k < NB; ++k) {
            ok &= fabsf(centers[h * NB + k] - (c0 + (float)k * d)) <= 1e-5f;
            ok &= fabsf(log_widths[h * NB + k] - lw0) <= 1e-6f;
        }
        if (!ok) atomicAnd(&s_ok, 0);
        float sp = (lw0 > 15.f) ? lw0 : log1pf(expf(lw0));
        float w  = sp + 0.001f;
        float sq = -1.4426950408889634f / (w * w);
        float A  = -2.f * sq * d;
        float B  = sq * d * d;
        float4 p1, p2;
        p1.x = c0 - in_b[h]; p1.y = sq; p1.z = d; p1.w = A;
        p2.x = B; p2.y = 2.f * B; p2.z = exp2f(2.f * B); p2.w = 0.f;
        g_p1[h] = p1; g_p2[h] = p2;
    }
    __syncthreads();
    if (tid == 0) g_flag = s_ok;
}

// ---- prep2: pre-split W into swizzled bf16 hi/lo tiles ----
__global__ void rbf_prep2(const float* __restrict__ in_w)
{
    int t = blockIdx.x * blockDim.x + threadIdx.x;    // 0..16383
    if (t >= NH * 256) return;
    int row = t >> 8;                 // h
    int c4g = t & 255;                // global float4 col
    int ch  = c4g >> 4;
    int c4  = c4g & 15;
    float4 v = ((const float4*)in_w)[row * 256 + c4g];
    uint32_t hi01, hi23, lo01, lo23;
    split_pack(v, hi01, hi23, lo01, lo23);
    uint32_t sw = ((uint32_t)row * 128u + (uint32_t)c4 * 8u) ^ ((uint32_t)(row & 7) << 4);
    unsigned char* base = g_wt + ch * 16384;
    *(uint2*)(base + sw)        = make_uint2(hi01, hi23);
    *(uint2*)(base + 8192 + sw) = make_uint2(lo01, lo23);
}

// ---- fused GEMM + RBF kernel ----
__global__ void __launch_bounds__(NT1, 2)
rbf_fused_kernel(const float* __restrict__ x,
                 const float* __restrict__ out_bias,
                 float* __restrict__ out)
{
    extern __shared__ char smem[];
    const uint32_t sb = smem_u32(smem);
    const int tid = threadIdx.x;
    const int wid = tid >> 5;
    const int l   = tid & 31;
    const int wq  = wid & 3;
    const int wh  = wid >> 2;
    const int tok0 = blockIdx.x * MTILE;

    const int r0  = tid >> 4;
    const int c4  = tid & 15;
    const uint32_t stc = (uint32_t)c4 * 8u;

    const uint32_t key  = (uint32_t)(l & 7);
    const uint32_t rowA = (uint32_t)(wq * 32 + (l & 15));
    const uint32_t chA  = (uint32_t)((l >> 4) & 1);
    const uint32_t rowB = (uint32_t)(wh * 32 + ((l >> 4) << 3) + (l & 7));
    const uint32_t chB  = (uint32_t)((l >> 3) & 1);

    float acc[2][4][4];
#pragma unroll
    for (int m = 0; m < 2; ++m)
#pragma unroll
        for (int nt = 0; nt < 4; ++nt)
#pragma unroll
            for (int j = 0; j < 4; ++j) acc[m][nt][j] = 0.f;

    const float4* xg = (const float4*)x;
    float4 pa[8];

    // ---- prologue: chunk 0 ----
    {
        const unsigned char* src = g_wt + (uint32_t)tid * 16u;
#pragma unroll
        for (int i = 0; i < 4; ++i)
            CP_ASYNC16(sb + OFF_BHI + (uint32_t)tid * 16u + i * 4096u, src + i * 4096);
        CP_COMMIT();
#pragma unroll
        for (int it = 0; it < 8; ++it)
            pa[it] = xg[(long)(tok0 + r0 + it * 16) * 256 + c4];
#pragma unroll
        for (int it = 0; it < 8; ++it) {
            int row = r0 + it * 16;
            uint32_t sw = ((uint32_t)row * 128u + stc) ^ ((uint32_t)(row & 7) << 4);
            split_store(pa[it], sb + OFF_AHI + sw, sb + OFF_ALO + sw);
        }
        CP_WAIT0();
        __syncthreads();
    }

#pragma unroll 1
    for (int ch = 0; ch < NCHUNKS; ++ch) {
        const uint32_t sbase = sb + (uint32_t)(ch & 1) * STAGE_BYTES;
        const uint32_t dbase = sb + (uint32_t)((ch + 1) & 1) * STAGE_BYTES;

        if (ch < NCHUNKS - 1) {
#pragma unroll
            for (int it = 0; it < 8; ++it)
                pa[it] = xg[(long)(tok0 + r0 + it * 16) * 256 + (ch + 1) * 16 + c4];
            const unsigned char* src = g_wt + (uint32_t)(ch + 1) * 16384u + (uint32_t)tid * 16u;
#pragma unroll
            for (int i = 0; i < 4; ++i)
                CP_ASYNC16(dbase + OFF_BHI + (uint32_t)tid * 16u + i * 4096u, src + i * 4096);
            CP_COMMIT();
        }

#pragma unroll
        for (int s = 0; s < 4; ++s) {
            const uint32_t colA = ((uint32_t)(s * 2) + chA) ^ key;
            const uint32_t colB = ((uint32_t)(s * 2) + chB) ^ key;
            uint32_t ah[2][4], al[2][4];
#pragma unroll
            for (int m = 0; m < 2; ++m) {
                uint32_t ra = (rowA + m * 16) * 128u + (colA << 4);
                LDSM4(ah[m][0], ah[m][1], ah[m][2], ah[m][3], sbase + OFF_AHI + ra);
                LDSM4(al[m][0], al[m][1], al[m][2], al[m][3], sbase + OFF_ALO + ra);
            }
#pragma unroll
            for (int np = 0; np < 2; ++np) {
                uint32_t rb = (rowB + np * 16) * 128u + (colB << 4);
                uint32_t bh[4], bl[4];
                LDSM4(bh[0], bh[1], bh[2], bh[3], sbase + OFF_BHI + rb);
                LDSM4(bl[0], bl[1], bl[2], bl[3], sbase + OFF_BHI + 8192u + rb);
#pragma unroll
                for (int m = 0; m < 2; ++m) {
                    MMA(acc[m][2 * np],     ah[m][0], ah[m][1], ah[m][2], ah[m][3], bh[0], bh[1]);
                    MMA(acc[m][2 * np + 1], ah[m][0], ah[m][1], ah[m][2], ah[m][3], bh[2], bh[3]);
                    MMA(acc[m][2 * np],     ah[m][0], ah[m][1], ah[m][2], ah[m][3], bl[0], bl[1]);
                    MMA(acc[m][2 * np + 1], ah[m][0], ah[m][1], ah[m][2], ah[m][3], bl[2], bl[3]);
                    MMA(acc[m][2 * np],     al[m][0], al[m][1], al[m][2], al[m][3], bh[0], bh[1]);
                    MMA(acc[m][2 * np + 1], al[m][0], al[m][1], al[m][2], al[m][3], bh[2], bh[3]);
                }
            }
            // interleave A stores for next chunk during s=2,3
            if (ch < NCHUNKS - 1 && s >= 2) {
#pragma unroll
                for (int j = 0; j < 4; ++j) {
                    int it = (s - 2) * 4 + j;
                    int row = r0 + it * 16;
                    uint32_t sw = ((uint32_t)row * 128u + stc) ^ ((uint32_t)(row & 7) << 4);
                    split_store(pa[it], dbase + OFF_AHI + sw, dbase + OFF_ALO + sw);
                }
            }
        }
        if (ch < NCHUNKS - 1) CP_WAIT0();
        __syncthreads();
    }

    // ---- overlay: z -> smem [128][66], stage tables ----
    {
        float* zs = (float*)(smem + OFF_ZS);
        const int g = l >> 2, t = l & 3;
#pragma unroll
        for (int m = 0; m < 2; ++m)
#pragma unroll
            for (int nt = 0; nt < 4; ++nt) {
                int tok = wq * 32 + m * 16 + g;
                int hcol = wh * 32 + nt * 8 + 2 * t;
                *(float2*)(zs + tok * 66 + hcol)       = make_float2(acc[m][nt][0], acc[m][nt][1]);
                *(float2*)(zs + (tok + 8) * 66 + hcol) = make_float2(acc[m][nt][2], acc[m][nt][3]);
            }
        float4* owt = (float4*)(smem + OFF_OWT);
        const float4* gow = (const float4*)g_owt;
#pragma unroll
        for (int j = 0; j < 4; ++j) owt[j * NT1 + tid] = gow[j * NT1 + tid];
        if (tid < NH) {
            ((float4*)(smem + OFF_P1))[tid] = g_p1[tid];
            ((float4*)(smem + OFF_P2))[tid] = g_p2[tid];
        }
    }
    __syncthreads();

    // ---- epilogue: thread = (token pair) x (16 h) ----
    const int hq = tid & 3;
    const int p  = tid >> 2;                 // tokens p and p+64
    const float* zs = (const float*)(smem + OFF_ZS);
    const float* zA = zs + p * 66 + hq * 16;
    const float* zB = zs + (p + 64) * 66 + hq * 16;
    const float4* p1s = (const float4*)(smem + OFF_P1);
    const float4* p2s = (const float4*)(smem + OFF_P2);
    float sumA, sumB;

    if (g_flag) {
        unsigned long long accA = 0ull, accB = 0ull;
#pragma unroll 1
        for (int hp = 0; hp < 8; ++hp) {
            const int h0 = hq * 16 + 2 * hp;
            float2 zzA = *(const float2*)(zA + 2 * hp);
            float2 zzB = *(const float2*)(zB + 2 * hp);
            float4 Pa = p1s[h0], Pb = p1s[h0 + 1];
            float4 Qa = p2s[h0], Qb = p2s[h0 + 1];
            float uA0 = zzA.x - Pa.x, uA1 = zzA.y - Pb.x;
            float uB0 = zzB.x - Pa.x, uB1 = zzB.y - Pb.x;
            float rbA0 = fmaf(Pa.w, uA0, Qa.x), rbA1 = fmaf(Pb.w, uA1, Qb.x);
            float rbB0 = fmaf(Pa.w, uB0, Qa.x), rbB1 = fmaf(Pb.w, uB1, Qb.x);
            unsigned long long tt;
            PACK2(tt, Qa.z, Qb.z);
            const uint32_t owbase = sb + OFF_OWT + (uint32_t)h0 * 4u;
#pragma unroll
            for (int m = 0; m < 4; ++m) {
                const float km = (float)(16 * m);
                float vA0 = fmaf(-km, Pa.z, uA0), vA1 = fmaf(-km, Pb.z, uA1);
                float vB0 = fmaf(-km, Pa.z, uB0), vB1 = fmaf(-km, Pb.z, uB1);
                float eA0, eA1, eB0, eB1, rA0, rA1, rB0, rB1;
                float aA0 = Pa.y * vA0 * vA0, aA1 = Pb.y * vA1 * vA1;
                float aB0 = Pa.y * vB0 * vB0, aB1 = Pb.y * vB1 * vB1;
                asm("ex2.approx.f32 %0, %1;" : "=f"(eA0) : "f"(aA0));
                asm("ex2.approx.f32 %0, %1;" : "=f"(eA1) : "f"(aA1));
                asm("ex2.approx.f32 %0, %1;" : "=f"(eB0) : "f"(aB0));
                asm("ex2.approx.f32 %0, %1;" : "=f"(eB1) : "f"(aB1));
                float bA0 = fmaf(km, Qa.y, rbA0), bA1 = fmaf(km, Qb.y, rbA1);
                float bB0 = fmaf(km, Qa.y, rbB0), bB1 = fmaf(km, Qb.y, rbB1);
                asm("ex2.approx.f32 %0, %1;" : "=f"(rA0) : "f"(bA0));
                asm("ex2.approx.f32 %0, %1;" : "=f"(rA1) : "f"(bA1));
                asm("ex2.approx.f32 %0, %1;" : "=f"(rB0) : "f"(bB0));
                asm("ex2.approx.f32 %0, %1;" : "=f"(rB1) : "f"(bB1));
                unsigned long long eA, rA, eB, rB;
                PACK2(eA, eA0, eA1); PACK2(rA, rA0, rA1);
                PACK2(eB, eB0, eB1); PACK2(rB, rB0, rB1);
                uint32_t a = owbase + (uint32_t)m * (16u * 256u);
#pragma unroll
                for (int kk = 0; kk < 16; ++kk) {
                    unsigned long long w2;
                    asm volatile("ld.shared.b64 %0, [%1];" : "=l"(w2) : "r"(a));
                    a += 256u;
                    FMA2(accA, eA, w2);
                    FMA2(accB, eB, w2);
                    MUL2(eA, eA, rA);
                    MUL2(eB, eB, rB);
                    MUL2(rA, rA, tt);
                    MUL2(rB, rB, tt);
                }
            }
        }
        float lo, hi;
        asm("mov.b64 {%0,%1}, %2;" : "=f"(lo), "=f"(hi) : "l"(accA));
        sumA = lo + hi;
        asm("mov.b64 {%0,%1}, %2;" : "=f"(lo), "=f"(hi) : "l"(accB));
        sumB = lo + hi;
    } else {
        sumA = 0.f; sumB = 0.f;
#pragma unroll 1
        for (int i = 0; i < 16; ++i) {
            const int h = hq * 16 + i;
            const float zhA = zA[i], zhB = zB[i];
            const float4* qh = g_q + h * NB;
#pragma unroll 8
            for (int k = 0; k < NB; ++k) {
                float4 q = qh[k];
                float pA = fmaf(fmaf(q.x, zhA, q.y), zhA, q.z);
                float pB = fmaf(fmaf(q.x, zhB, q.y), zhB, q.z);
                float eA, eB;
                asm("ex2.approx.f32 %0, %1;" : "=f"(eA) : "f"(pA));
                asm("ex2.approx.f32 %0, %1;" : "=f"(eB) : "f"(pB));
                sumA = fmaf(eA, q.w, sumA);
                sumB = fmaf(eB, q.w, sumB);
            }
        }
    }

    sumA += __shfl_xor_sync(0xffffffffu, sumA, 1);
    sumA += __shfl_xor_sync(0xffffffffu, sumA, 2);
    sumB += __shfl_xor_sync(0xffffffffu, sumB, 1);
    sumB += __shfl_xor_sync(0xffffffffu, sumB, 2);
    if (hq == 0) {
        const float ob = __ldg(out_bias);
        out[tok0 + p]      = sumA + ob;
        out[tok0 + p + 64] = sumB + ob;
    }
}

extern "C" void kernel_launch(void* const* d_in, const int* in_sizes, int n_in,
                              void* d_out, int out_size)
{
    const float* x          = (const float*)d_in[0];
    const float* in_w       = (const float*)d_in[1];
    const float* in_b       = (const float*)d_in[2];
    const float* centers    = (const float*)d_in[3];
    const float* log_widths = (const float*)d_in[4];
    const float* out_weight = (const float*)d_in[5];
    const float* out_bias   = (const float*)d_in[6];
    float* out = (float*)d_out;

    int ntok = in_sizes[0] / DIMC;          // 65536

    rbf_prep1<<<1, 256>>>(in_b, centers, log_widths, out_weight);
    rbf_prep2<<<64, 256>>>(in_w);

    cudaFuncSetAttribute(rbf_fused_kernel,
                         cudaFuncAttributeMaxDynamicSharedMemorySize, SMEM_TOTAL);
    rbf_fused_kernel<<<ntok / MTILE, NT1, SMEM_TOTAL>>>(x, out_bias, out);
}

// round 8
// speedup vs baseline: 2.7245x; 1.0358x over previous
#include <cuda_runtime.h>
#include <cstdint>

#define NT1      256
#define MTILE    128
#define NCHUNKS  16
#define NH       64
#define NB       64
#define DIMC     1024

// stage layout (two stages)
#define STAGE_BYTES 49152
#define OFF_AHI  0
#define OFF_ALO  16384
#define OFF_BHI  32768          // B hi (8 KB) + B lo (8 KB) contiguous
// post-GEMM overlay
#define OFF_ZS   0              // float[128*66] = 33792 B
#define OFF_OWT  34816          // float[64*64]  = 16384 B
#define OFF_P1   51200
#define OFF_P2   52224
#define SMEM_TOTAL (2 * STAGE_BYTES)

__device__ float4 g_q[NH * NB];
__device__ float  g_owt[NH * NB];          // out_weight transposed [k][h]
__device__ float4 g_p1[NH];                // {c0', sq, d, A}
__device__ float4 g_p2[NH];                // {B, 2B, 2^{2B}, 0}
__device__ int    g_bad = 0;               // add-only failure counter (deterministic inputs)
__device__ __align__(16) unsigned char g_wt[NCHUNKS * 16384];  // pre-split W tiles

static __device__ __forceinline__ uint32_t smem_u32(const void* p) {
    uint32_t a;
    asm("{ .reg .u64 t; cvta.to.shared.u64 t, %1; cvt.u32.u64 %0, t; }" : "=r"(a) : "l"(p));
    return a;
}

#define FMA2(acc, a, b) asm("fma.rn.f32x2 %0, %1, %2, %0;" : "+l"(acc) : "l"(a), "l"(b))
#define MUL2(d, a, b)   asm("mul.rn.f32x2 %0, %1, %2;" : "=l"(d) : "l"(a), "l"(b))
#define PACK2(d, lo, hi) asm("mov.b64 %0, {%1, %2};" : "=l"(d) : "f"(lo), "f"(hi))

#define CP_ASYNC16(dst, src) \
    asm volatile("cp.async.ca.shared.global [%0], [%1], 16;" :: "r"(dst), "l"(src) : "memory")
#define CP_COMMIT() asm volatile("cp.async.commit_group;" ::: "memory")
#define CP_WAIT0()  asm volatile("cp.async.wait_group 0;" ::: "memory")

static __device__ __forceinline__ void split_pack(float4 v, uint32_t& hi01, uint32_t& hi23,
                                                  uint32_t& lo01, uint32_t& lo23) {
    uint32_t u0 = __float_as_uint(v.x), u1 = __float_as_uint(v.y);
    uint32_t u2 = __float_as_uint(v.z), u3 = __float_as_uint(v.w);
    hi01 = __byte_perm(u0, u1, 0x7632);
    hi23 = __byte_perm(u2, u3, 0x7632);
    float l0 = v.x - __uint_as_float(u0 & 0xffff0000u);
    float l1 = v.y - __uint_as_float(u1 & 0xffff0000u);
    float l2 = v.z - __uint_as_float(u2 & 0xffff0000u);
    float l3 = v.w - __uint_as_float(u3 & 0xffff0000u);
    asm("cvt.rn.bf16x2.f32 %0, %1, %2;" : "=r"(lo01) : "f"(l1), "f"(l0));
    asm("cvt.rn.bf16x2.f32 %0, %1, %2;" : "=r"(lo23) : "f"(l3), "f"(l2));
}

static __device__ __forceinline__ void split_store(float4 v, uint32_t ahi, uint32_t alo) {
    uint32_t hi01, hi23, lo01, lo23;
    split_pack(v, hi01, hi23, lo01, lo23);
    asm volatile("st.shared.v2.b32 [%0], {%1,%2};" :: "r"(ahi), "r"(hi01), "r"(hi23) : "memory");
    asm volatile("st.shared.v2.b32 [%0], {%1,%2};" :: "r"(alo), "r"(lo01), "r"(lo23) : "memory");
}

#define LDSM4(r0, r1, r2, r3, a) \
    asm volatile("ldmatrix.sync.aligned.m8n8.x4.shared.b16 {%0,%1,%2,%3}, [%4];" \
                 : "=r"(r0), "=r"(r1), "=r"(r2), "=r"(r3) : "r"(a))

#define MMA(c, a0, a1, a2, a3, b0, b1) \
    asm volatile("mma.sync.aligned.m16n8k16.row.col.f32.bf16.bf16.f32 " \
                 "{%0,%1,%2,%3}, {%4,%5,%6,%7}, {%8,%9}, {%0,%1,%2,%3};" \
                 : "+f"((c)[0]), "+f"((c)[1]), "+f"((c)[2]), "+f"((c)[3]) \
                 : "r"(a0), "r"(a1), "r"(a2), "r"(a3), "r"(b0), "r"(b1))

// ---- single prep kernel: blocks 0-63 split W; blocks 64-79 build tables ----
__global__ void rbf_prep(const float* __restrict__ in_b,
                         const float* __restrict__ centers,
                         const float* __restrict__ log_widths,
                         const float* __restrict__ out_weight,
                         const float* __restrict__ in_w)
{
    const int bid = blockIdx.x;
    const int tid = threadIdx.x;

    if (bid < 64) {
        // pre-split W into swizzled bf16 hi/lo tiles
        int t = bid * 256 + tid;          // 0..16383
        int row = t >> 8;                 // h
        int c4g = t & 255;
        int ch  = c4g >> 4;
        int c4  = c4g & 15;
        float4 v = ((const float4*)in_w)[row * 256 + c4g];
        uint32_t hi01, hi23, lo01, lo23;
        split_pack(v, hi01, hi23, lo01, lo23);
        uint32_t sw = ((uint32_t)row * 128u + (uint32_t)c4 * 8u) ^ ((uint32_t)(row & 7) << 4);
        unsigned char* base = g_wt + ch * 16384;
        *(uint2*)(base + sw)        = make_uint2(hi01, hi23);
        *(uint2*)(base + 8192 + sw) = make_uint2(lo01, lo23);
        return;
    }

    const int i = (bid - 64) * 256 + tid;   // 0..4095
    const int h = i >> 6;
    const int k = i & 63;

    float lw = log_widths[i];
    float sp = (lw > 15.f) ? lw : log1pf(expf(lw));
    float w = sp + 0.001f;
    float s = -1.4426950408889634f / (w * w);
    float c = centers[i] - in_b[h];
    float4 q;
    q.x = s; q.y = -2.f * s * c; q.z = s * c * c; q.w = out_weight[i];
    g_q[i] = q;
    g_owt[i] = out_weight[((i & 63) << 6) + (i >> 6)];

    // per-element structure validation
    float c0  = centers[h * NB];
    float d   = (centers[h * NB + NB - 1] - c0) / (float)(NB - 1);
    float lw0 = log_widths[h * NB];
    bool ok = (fabsf(centers[i] - fmaf((float)k, d, c0)) <= 1e-5f) &&
              (fabsf(lw - lw0) <= 1e-6f);
    if (!ok) atomicAdd(&g_bad, 1);

    // per-h recurrence params
    if (k == 0) {
        float sp0 = (lw0 > 15.f) ? lw0 : log1pf(expf(lw0));
        float w0  = sp0 + 0.001f;
        float sq  = -1.4426950408889634f / (w0 * w0);
        float A   = -2.f * sq * d;
        float B   = sq * d * d;
        float4 p1, p2;
        p1.x = c0 - in_b[h]; p1.y = sq; p1.z = d; p1.w = A;
        p2.x = B; p2.y = 2.f * B; p2.z = exp2f(2.f * B); p2.w = 0.f;
        g_p1[h] = p1; g_p2[h] = p2;
    }
}

// ---- fused GEMM + RBF kernel ----
__global__ void __launch_bounds__(NT1, 2)
rbf_fused_kernel(const float* __restrict__ x,
                 const float* __restrict__ out_bias,
                 float* __restrict__ out)
{
    extern __shared__ char smem[];
    const uint32_t sb = smem_u32(smem);
    const int tid = threadIdx.x;
    const int wid = tid >> 5;
    const int l   = tid & 31;
    const int wq  = wid & 3;
    const int wh  = wid >> 2;
    const int tok0 = blockIdx.x * MTILE;

    const int r0  = tid >> 4;
    const int c4  = tid & 15;
    const uint32_t stc = (uint32_t)c4 * 8u;

    const uint32_t key  = (uint32_t)(l & 7);
    const uint32_t rowA = (uint32_t)(wq * 32 + (l & 15));
    const uint32_t chA  = (uint32_t)((l >> 4) & 1);
    const uint32_t rowB = (uint32_t)(wh * 32 + ((l >> 4) << 3) + (l & 7));
    const uint32_t chB  = (uint32_t)((l >> 3) & 1);

    float acc[2][4][4];
#pragma unroll
    for (int m = 0; m < 2; ++m)
#pragma unroll
        for (int nt = 0; nt < 4; ++nt)
#pragma unroll
            for (int j = 0; j < 4; ++j) acc[m][nt][j] = 0.f;

    const float4* xg = (const float4*)x;
    float4 pa[8];

    // ---- prologue: chunk 0 ----
    {
        const unsigned char* src = g_wt + (uint32_t)tid * 16u;
#pragma unroll
        for (int i = 0; i < 4; ++i)
            CP_ASYNC16(sb + OFF_BHI + (uint32_t)tid * 16u + i * 4096u, src + i * 4096);
        CP_COMMIT();
#pragma unroll
        for (int it = 0; it < 8; ++it)
            pa[it] = xg[(long)(tok0 + r0 + it * 16) * 256 + c4];
#pragma unroll
        for (int it = 0; it < 8; ++it) {
            int row = r0 + it * 16;
            uint32_t sw = ((uint32_t)row * 128u + stc) ^ ((uint32_t)(row & 7) << 4);
            split_store(pa[it], sb + OFF_AHI + sw, sb + OFF_ALO + sw);
        }
        CP_WAIT0();
        __syncthreads();
    }

#pragma unroll 1
    for (int ch = 0; ch < NCHUNKS; ++ch) {
        const uint32_t sbase = sb + (uint32_t)(ch & 1) * STAGE_BYTES;
        const uint32_t dbase = sb + (uint32_t)((ch + 1) & 1) * STAGE_BYTES;

        if (ch < NCHUNKS - 1) {
#pragma unroll
            for (int it = 0; it < 8; ++it)
                pa[it] = xg[(long)(tok0 + r0 + it * 16) * 256 + (ch + 1) * 16 + c4];
            const unsigned char* src = g_wt + (uint32_t)(ch + 1) * 16384u + (uint32_t)tid * 16u;
#pragma unroll
            for (int i = 0; i < 4; ++i)
                CP_ASYNC16(dbase + OFF_BHI + (uint32_t)tid * 16u + i * 4096u, src + i * 4096);
            CP_COMMIT();
        }

#pragma unroll
        for (int s = 0; s < 4; ++s) {
            const uint32_t colA = ((uint32_t)(s * 2) + chA) ^ key;
            const uint32_t colB = ((uint32_t)(s * 2) + chB) ^ key;
            uint32_t ah[2][4], al[2][4];
#pragma unroll
            for (int m = 0; m < 2; ++m) {
                uint32_t ra = (rowA + m * 16) * 128u + (colA << 4);
                LDSM4(ah[m][0], ah[m][1], ah[m][2], ah[m][3], sbase + OFF_AHI + ra);
                LDSM4(al[m][0], al[m][1], al[m][2], al[m][3], sbase + OFF_ALO + ra);
            }
#pragma unroll
            for (int np = 0; np < 2; ++np) {
                uint32_t rb = (rowB + np * 16) * 128u + (colB << 4);
                uint32_t bh[4], bl[4];
                LDSM4(bh[0], bh[1], bh[2], bh[3], sbase + OFF_BHI + rb);
                LDSM4(bl[0], bl[1], bl[2], bl[3], sbase + OFF_BHI + 8192u + rb);
#pragma unroll
                for (int m = 0; m < 2; ++m) {
                    MMA(acc[m][2 * np],     ah[m][0], ah[m][1], ah[m][2], ah[m][3], bh[0], bh[1]);
                    MMA(acc[m][2 * np + 1], ah[m][0], ah[m][1], ah[m][2], ah[m][3], bh[2], bh[3]);
                    MMA(acc[m][2 * np],     ah[m][0], ah[m][1], ah[m][2], ah[m][3], bl[0], bl[1]);
                    MMA(acc[m][2 * np + 1], ah[m][0], ah[m][1], ah[m][2], ah[m][3], bl[2], bl[3]);
                    MMA(acc[m][2 * np],     al[m][0], al[m][1], al[m][2], al[m][3], bh[0], bh[1]);
                    MMA(acc[m][2 * np + 1], al[m][0], al[m][1], al[m][2], al[m][3], bh[2], bh[3]);
                }
            }
            if (ch < NCHUNKS - 1 && s >= 2) {
#pragma unroll
                for (int j = 0; j < 4; ++j) {
                    int it = (s - 2) * 4 + j;
                    int row = r0 + it * 16;
                    uint32_t sw = ((uint32_t)row * 128u + stc) ^ ((uint32_t)(row & 7) << 4);
                    split_store(pa[it], dbase + OFF_AHI + sw, dbase + OFF_ALO + sw);
                }
            }
        }
        if (ch < NCHUNKS - 1) CP_WAIT0();
        __syncthreads();
    }

    // ---- overlay: z -> smem [128][66], stage tables ----
    {
        float* zs = (float*)(smem + OFF_ZS);
        const int g = l >> 2, t = l & 3;
#pragma unroll
        for (int m = 0; m < 2; ++m)
#pragma unroll
            for (int nt = 0; nt < 4; ++nt) {
                int tok = wq * 32 + m * 16 + g;
                int hcol = wh * 32 + nt * 8 + 2 * t;
                *(float2*)(zs + tok * 66 + hcol)       = make_float2(acc[m][nt][0], acc[m][nt][1]);
                *(float2*)(zs + (tok + 8) * 66 + hcol) = make_float2(acc[m][nt][2], acc[m][nt][3]);
            }
        float4* owt = (float4*)(smem + OFF_OWT);
        const float4* gow = (const float4*)g_owt;
#pragma unroll
        for (int j = 0; j < 4; ++j) owt[j * NT1 + tid] = gow[j * NT1 + tid];
        if (tid < NH) {
            ((float4*)(smem + OFF_P1))[tid] = g_p1[tid];
            ((float4*)(smem + OFF_P2))[tid] = g_p2[tid];
        }
    }
    __syncthreads();

    // ---- epilogue: thread = 4 tokens x 8 h ----
    const int hq = tid & 7;                  // h group: h = hq*8 .. hq*8+7
    const int p  = tid >> 3;                 // tokens p + 32*j
    const float* zs = (const float*)(smem + OFF_ZS);
    const float4* p1s = (const float4*)(smem + OFF_P1);
    const float4* p2s = (const float4*)(smem + OFF_P2);
    float sum[4];

    if (g_bad == 0) {
        unsigned long long acc2[4] = {0ull, 0ull, 0ull, 0ull};
#pragma unroll
        for (int hp = 0; hp < 4; ++hp) {
            const int h0 = hq * 8 + 2 * hp;
            float4 Pa = p1s[h0], Pb = p1s[h0 + 1];
            float4 Qa = p2s[h0], Qb = p2s[h0 + 1];
            unsigned long long tt;
            PACK2(tt, Qa.z, Qb.z);
            float u0[4], u1[4], rb0[4], rb1[4];
#pragma unroll
            for (int j = 0; j < 4; ++j) {
                float2 zz = *(const float2*)(zs + (p + 32 * j) * 66 + h0);
                u0[j] = zz.x - Pa.x;  u1[j] = zz.y - Pb.x;
                rb0[j] = fmaf(Pa.w, u0[j], Qa.x);
                rb1[j] = fmaf(Pb.w, u1[j], Qb.x);
            }
            const uint32_t owbase = sb + OFF_OWT + (uint32_t)h0 * 4u;
#pragma unroll
            for (int m = 0; m < 4; ++m) {
                const float km = (float)(16 * m);
                unsigned long long e[4], r[4];
#pragma unroll
                for (int j = 0; j < 4; ++j) {
                    float v0 = fmaf(-km, Pa.z, u0[j]);
                    float v1 = fmaf(-km, Pb.z, u1[j]);
                    float e0, e1, rr0, rr1;
                    float a0 = Pa.y * v0 * v0, a1 = Pb.y * v1 * v1;
                    asm("ex2.approx.f32 %0, %1;" : "=f"(e0) : "f"(a0));
                    asm("ex2.approx.f32 %0, %1;" : "=f"(e1) : "f"(a1));
                    float b0 = fmaf(km, Qa.y, rb0[j]), b1 = fmaf(km, Qb.y, rb1[j]);
                    asm("ex2.approx.f32 %0, %1;" : "=f"(rr0) : "f"(b0));
                    asm("ex2.approx.f32 %0, %1;" : "=f"(rr1) : "f"(b1));
                    PACK2(e[j], e0, e1);
                    PACK2(r[j], rr0, rr1);
                }
                uint32_t a = owbase + (uint32_t)m * (16u * 256u);
#pragma unroll
                for (int kk = 0; kk < 16; ++kk) {
                    unsigned long long w2;
                    asm volatile("ld.shared.b64 %0, [%1];" : "=l"(w2) : "r"(a));
                    a += 256u;
#pragma unroll
                    for (int j = 0; j < 4; ++j) {
                        FMA2(acc2[j], e[j], w2);
                        MUL2(e[j], e[j], r[j]);
                        MUL2(r[j], r[j], tt);
                    }
                }
            }
        }
#pragma unroll
        for (int j = 0; j < 4; ++j) {
            float lo, hi;
            asm("mov.b64 {%0,%1}, %2;" : "=f"(lo), "=f"(hi) : "l"(acc2[j]));
            sum[j] = lo + hi;
        }
    } else {
#pragma unroll
        for (int j = 0; j < 4; ++j) sum[j] = 0.f;
#pragma unroll 1
        for (int i = 0; i < 8; ++i) {
            const int h = hq * 8 + i;
            const float4* qh = g_q + h * NB;
            float zh[4];
#pragma unroll
            for (int j = 0; j < 4; ++j) zh[j] = zs[(p + 32 * j) * 66 + h];
#pragma unroll 8
            for (int k = 0; k < NB; ++k) {
                float4 q = qh[k];
#pragma unroll
                for (int j = 0; j < 4; ++j) {
                    float pp = fmaf(fmaf(q.x, zh[j], q.y), zh[j], q.z);
                    float e;
                    asm("ex2.approx.f32 %0, %1;" : "=f"(e) : "f"(pp));
                    sum[j] = fmaf(e, q.w, sum[j]);
                }
            }
        }
    }

    const float ob = __ldg(out_bias);
#pragma unroll
    for (int j = 0; j < 4; ++j) {
        float v = sum[j];
        v += __shfl_xor_sync(0xffffffffu, v, 1);
        v += __shfl_xor_sync(0xffffffffu, v, 2);
        v += __shfl_xor_sync(0xffffffffu, v, 4);
        if (hq == 0) out[tok0 + p + 32 * j] = v + ob;
    }
}

extern "C" void kernel_launch(void* const* d_in, const int* in_sizes, int n_in,
                              void* d_out, int out_size)
{
    const float* x          = (const float*)d_in[0];
    const float* in_w       = (const float*)d_in[1];
    const float* in_b       = (const float*)d_in[2];
    const float* centers    = (const float*)d_in[3];
    const float* log_widths = (const float*)d_in[4];
    const float* out_weight = (const float*)d_in[5];
    const float* out_bias   = (const float*)d_in[6];
    float* out = (float*)d_out;

    int ntok = in_sizes[0] / DIMC;          // 65536

    rbf_prep<<<80, 256>>>(in_b, centers, log_widths, out_weight, in_w);

    cudaFuncSetAttribute(rbf_fused_kernel,
                         cudaFuncAttributeMaxDynamicSharedMemorySize, SMEM_TOTAL);
    rbf_fused_kernel<<<ntok / MTILE, NT1, SMEM_TOTAL>>>(x, out_bias, out);
}